// round 7
// baseline (speedup 1.0000x reference)
#include <cuda_runtime.h>
#include <cstdint>

#define SQ    2048
#define EB    2048
#define BATCH 2
#define NH    16
#define NKV   4
#define HD    128
#define KVDIM (NKV*HD)

// Scratch (device globals — allocation inside kernel_launch is forbidden)
__device__ float g_q[BATCH * SQ * NH * HD];     // 32 MB
__device__ float g_k[BATCH * SQ * NKV * HD];    //  8 MB
__device__ float g_v[BATCH * SQ * NKV * HD];    //  8 MB
__device__ float g_attn[BATCH * SQ * EB];       // 32 MB
__device__ float g_wt[EB * 3072];               // 25 MB (fragment-packed weights)

// ---------------------------------------------------------------------------
__device__ __forceinline__ uint32_t smem_u32(const void* p) {
    uint32_t a;
    asm("{ .reg .u64 t; cvta.to.shared.u64 t, %1; cvt.u32.u64 %0, t; }"
        : "=r"(a) : "l"(p));
    return a;
}

__device__ __forceinline__ uint32_t to_tf32(float x) {
    uint32_t r;
    asm("cvt.rna.tf32.f32 %0, %1;" : "=r"(r) : "f"(x));
    return r;
}

__device__ __forceinline__ uint4 cvt4(float4 v) {
    uint4 u;
    u.x = to_tf32(v.x); u.y = to_tf32(v.y);
    u.z = to_tf32(v.z); u.w = to_tf32(v.w);
    return u;
}

__device__ __forceinline__ void cp_async16(uint32_t smem_addr, const void* gptr) {
    asm volatile("cp.async.cg.shared.global [%0], [%1], 16;"
                 :: "r"(smem_addr), "l"(gptr));
}

__device__ __forceinline__ void mma168(float4& d, const uint32_t* a, uint2 b) {
    asm volatile(
        "mma.sync.aligned.m16n8k8.row.col.f32.tf32.tf32.f32 "
        "{%0,%1,%2,%3}, {%4,%5,%6,%7}, {%8,%9}, {%0,%1,%2,%3};"
        : "+f"(d.x), "+f"(d.y), "+f"(d.z), "+f"(d.w)
        : "r"(a[0]), "r"(a[1]), "r"(a[2]), "r"(a[3]), "r"(b.x), "r"(b.y));
}

// ---------------------------------------------------------------------------
// Pack W[k][n] (row-major KxN fp32) into per-fragment tf32 layout.
// ---------------------------------------------------------------------------
__global__ void pack_b(const float* __restrict__ W, float* __restrict__ Bp,
                       int K, int N)
{
    int gid = blockIdx.x * blockDim.x + threadIdx.x;
    int total = (K * N) >> 1;
    if (gid >= total) return;
    const int KC = K / 32;
    int t  = gid & 31;
    int ks = (gid >> 5) & 3;
    int nt = (gid >> 7) & 15;
    int kc = (gid >> 11) % KC;
    int np = (gid >> 11) / KC;
    int n = np * 128 + nt * 8 + (t >> 2);
    int k = kc * 32 + ks * 8 + (t & 3);
    float v0 = W[(size_t)k * N + n];
    float v1 = W[(size_t)(k + 4) * N + n];
    ((uint2*)Bp)[gid] = make_uint2(to_tf32(v0), to_tf32(v1));
}

// ---------------------------------------------------------------------------
// TF32 GEMM v3: C[M,N] = A[M,K] @ B[K,N].
// CTA tile 256x128, 512 threads = 16 warps (wm=wid&3 rows, wn=wid>>2 cols).
// Warp tile 64x32 (mt=4, nt=4), acc = 64 regs -> fits 128-reg cap at 512 thr.
// 4-stage cp.async pipeline, one __syncthreads per 32-K chunk.
// ---------------------------------------------------------------------------
#define GEMM_SMEM 212992
#define GST 13312

__device__ __forceinline__ void gemm_issue(
    const float* __restrict__ A, const float* __restrict__ Bp,
    uint32_t sb, int c, int tm0, int np, int K, int KC, int tid)
{
    const int st = c & 3;
    const uint32_t ab = sb + (st * GST) * 4;
    const uint32_t bb = sb + (st * GST + 9216) * 4;
#pragma unroll
    for (int i = 0; i < 4; i++) {
        int f = i * 512 + tid;
        int row = f >> 3, col4 = (f & 7) * 4;
        cp_async16(ab + (row * 36 + col4) * 4,
                   A + (size_t)(tm0 + row) * K + c * 32 + col4);
    }
#pragma unroll
    for (int i = 0; i < 2; i++) {
        int f = i * 512 + tid;
        cp_async16(bb + f * 16,
                   Bp + ((size_t)np * KC + c) * 4096 + f * 4);
    }
    asm volatile("cp.async.commit_group;" ::: "memory");
}

__global__ __launch_bounds__(512, 1) void gemm_mma(
    const float* __restrict__ A, const float* __restrict__ Bp,
    float* __restrict__ C0, float* __restrict__ C1, float* __restrict__ C2,
    int M, int N, int K, int fused)
{
    extern __shared__ float sm[];
    const int tid = threadIdx.x;
    const int lane = tid & 31, wid = tid >> 5;
    const int g = lane >> 2, t = lane & 3;
    const int wm = wid & 3, wn = wid >> 2;
    const int tm0 = blockIdx.y * 256, tn0 = blockIdx.x * 128;
    const int np = blockIdx.x;
    const int KC = K / 32;
    const uint32_t sb = smem_u32(sm);

    float4 acc[4][4];
#pragma unroll
    for (int i = 0; i < 4; i++)
#pragma unroll
        for (int j = 0; j < 4; j++) acc[i][j] = make_float4(0.f, 0.f, 0.f, 0.f);

    gemm_issue(A, Bp, sb, 0, tm0, np, K, KC, tid);
    gemm_issue(A, Bp, sb, 1, tm0, np, K, KC, tid);
    gemm_issue(A, Bp, sb, 2, tm0, np, K, KC, tid);

    const int r0 = wm * 64 + g;

    for (int c = 0; c < KC; c++) {
        const int rem = KC - 1 - c;
        if (rem >= 2)      asm volatile("cp.async.wait_group 2;" ::: "memory");
        else if (rem == 1) asm volatile("cp.async.wait_group 1;" ::: "memory");
        else               asm volatile("cp.async.wait_group 0;" ::: "memory");
        __syncthreads();

        const float* As = sm + (c & 3) * GST;
        const float* Bs = As + 9216;

#pragma unroll
        for (int ks = 0; ks < 4; ks++) {
            const int c0 = ks * 8 + t;
            uint32_t af[4][4];
#pragma unroll
            for (int mt = 0; mt < 4; mt++) {
                const int rb = (r0 + mt * 16) * 36;
                af[mt][0] = to_tf32(As[rb + c0]);
                af[mt][1] = to_tf32(As[rb + 8 * 36 + c0]);
                af[mt][2] = to_tf32(As[rb + c0 + 4]);
                af[mt][3] = to_tf32(As[rb + 8 * 36 + c0 + 4]);
            }
#pragma unroll
            for (int nt = 0; nt < 4; nt++) {
                uint2 bf = *(const uint2*)&Bs[(((wn * 4 + nt) * 4 + ks) * 32 + lane) * 2];
                mma168(acc[0][nt], af[0], bf);
                mma168(acc[1][nt], af[1], bf);
                mma168(acc[2][nt], af[2], bf);
                mma168(acc[3][nt], af[3], bf);
            }
        }

        if (c + 3 < KC)
            gemm_issue(A, Bp, sb, c + 3, tm0, np, K, KC, tid);
    }

    float* Cd; int ldc, coff;
    if (!fused)            { Cd = C0; ldc = N;    coff = 0;    }
    else if (tn0 < 2048)   { Cd = C0; ldc = 2048; coff = 0;    }
    else if (tn0 < 2560)   { Cd = C1; ldc = 512;  coff = 2048; }
    else                   { Cd = C2; ldc = 512;  coff = 2560; }

#pragma unroll
    for (int mt = 0; mt < 4; mt++) {
#pragma unroll
        for (int nt = 0; nt < 4; nt++) {
            int row = tm0 + wm * 64 + mt * 16 + g;
            int col = tn0 + wn * 32 + nt * 8 + t * 2 - coff;
            float4 a = acc[mt][nt];
            *(float2*)&Cd[(size_t)row * ldc + col] = make_float2(a.x, a.y);
            *(float2*)&Cd[(size_t)(row + 8) * ldc + col] = make_float2(a.z, a.w);
        }
    }
}

// ---------------------------------------------------------------------------
// RoPE on q (folds in 1/sqrt(HD) scale) and k, in place.
// ---------------------------------------------------------------------------
__global__ void rope_kernel(float* __restrict__ q, float* __restrict__ k)
{
    const int NQ = BATCH * SQ * NH * 64;
    const int NK = BATCH * SQ * NKV * 64;
    int i = blockIdx.x * blockDim.x + threadIdx.x;
    if (i >= NQ + NK) return;

    float* base;
    int d, s;
    float scale;
    if (i < NQ) {
        d = i & 63;
        int rest = i >> 6;
        s = (rest >> 4) & (SQ - 1);
        base = q + (size_t)rest * HD;
        scale = 0.08838834764831845f;
    } else {
        int j = i - NQ;
        d = j & 63;
        int rest = j >> 6;
        s = (rest >> 2) & (SQ - 1);
        base = k + (size_t)rest * HD;
        scale = 1.0f;
    }
    float inv_freq = powf(10000.0f, -(float)d * (1.0f / 64.0f));
    float ang = (float)s * inv_freq;
    float c = cosf(ang), sn = sinf(ang);
    float a = base[d], b = base[d + 64];
    base[d]      = (a * c - b * sn) * scale;
    base[d + 64] = (b * c + a * sn) * scale;
}

// ---------------------------------------------------------------------------
// Tensor-core flash attention v2 (tf32 mma) — unchanged from R6 (passing).
// ---------------------------------------------------------------------------
#define QS_OFF 0
#define K0_OFF 16896
#define K1_OFF 25344
#define VS_OFF 33792
#define PS_OFF 42496
#define MB_OFF 51200
#define LB_OFF 51456
#define ATT_SMEM (51712 * 4)

__global__ __launch_bounds__(256, 1) void attn_mma(
    const float* __restrict__ q, const float* __restrict__ k,
    const float* __restrict__ v, float* __restrict__ out)
{
    extern __shared__ float sm[];
    uint32_t* smu = (uint32_t*)sm;
    const int tid = threadIdx.x;
    const int lane = tid & 31, wid = tid >> 5;
    const int g = lane >> 2, t = lane & 3;
    const int wm = wid & 3, wn = wid >> 2;
    const int qt = gridDim.x - 1 - blockIdx.x;   // LPT: heavy tiles first
    const int h = blockIdx.y, b = blockIdx.z;
    const int kvh = h >> 2;
    const int q0 = qt * 128;

    const float4* q4 = (const float4*)q;
    const float4* k4 = (const float4*)k;
    const float4* v4 = (const float4*)v;

    const int ldrow = tid >> 5, ldc = tid & 31;

    // ---- prologue: Q tile (tf32) + K tile 0 into K0 ----
#pragma unroll
    for (int i = 0; i < 16; i++) {
        int f = i * 256 + tid;
        int row = f >> 5, c = f & 31;
        float4 vv = q4[((size_t)(b * SQ + q0 + row) * NH + h) * 32 + c];
        *(uint4*)&smu[QS_OFF + row * 132 + c * 4] = cvt4(vv);
    }
#pragma unroll
    for (int i = 0; i < 8; i++) {
        int row = i * 8 + ldrow;
        float4 kv = k4[((size_t)(b * SQ + row) * NKV + kvh) * 32 + ldc];
        *(uint4*)&smu[K0_OFF + row * 132 + ldc * 4] = cvt4(kv);
    }
    __syncthreads();

    float4 oacc[2][8];
#pragma unroll
    for (int i = 0; i < 2; i++)
#pragma unroll
        for (int j = 0; j < 8; j++) oacc[i][j] = make_float4(0.f, 0.f, 0.f, 0.f);
    float m_s[2][2] = {{-1e30f, -1e30f}, {-1e30f, -1e30f}};
    float l_s[2][2] = {{0.f, 0.f}, {0.f, 0.f}};

    const int r0 = wm * 32 + g;
    const int ntiles = 2 * qt + 2;

    for (int kt = 0; kt < ntiles; kt++) {
        const int k0 = kt * 64;
        const int KB = (kt & 1) ? K1_OFF : K0_OFF;

        // (1) stage V(kt): full 64x128 tile, 8 float4/thread
        float4 vreg[8];
#pragma unroll
        for (int i = 0; i < 8; i++)
            vreg[i] = v4[((size_t)(b * SQ + k0 + i * 8 + ldrow) * NKV + kvh) * 32 + ldc];

        // (2) S = Q @ K^T
        float4 sacc[2][4];
#pragma unroll
        for (int i = 0; i < 2; i++)
#pragma unroll
            for (int j = 0; j < 4; j++) sacc[i][j] = make_float4(0.f, 0.f, 0.f, 0.f);
#pragma unroll
        for (int ks = 0; ks < 16; ks++) {
            const int c0 = ks * 8 + t;
            uint32_t af[2][4];
#pragma unroll
            for (int mt = 0; mt < 2; mt++) {
                int rb = QS_OFF + (r0 + mt * 16) * 132 + c0;
                af[mt][0] = smu[rb];
                af[mt][1] = smu[rb + 132 * 8];
                af[mt][2] = smu[rb + 4];
                af[mt][3] = smu[rb + 132 * 8 + 4];
            }
#pragma unroll
            for (int nt = 0; nt < 4; nt++) {
                int nb = KB + (wn * 32 + nt * 8 + g) * 132 + c0;
                uint2 bf = make_uint2(smu[nb], smu[nb + 4]);
                mma168(sacc[0][nt], af[0], bf);
                mma168(sacc[1][nt], af[1], bf);
            }
        }

        // (3) causal mask + row max -> MB
        if (kt >= 2 * qt) {
#pragma unroll
            for (int mt = 0; mt < 2; mt++)
#pragma unroll
                for (int nt = 0; nt < 4; nt++) {
                    int colb = k0 + wn * 32 + nt * 8 + 2 * t;
                    int rowb = q0 + wm * 32 + mt * 16 + g;
                    float* sc = (float*)&sacc[mt][nt];
                    if (colb     > rowb)     sc[0] = -1e30f;
                    if (colb + 1 > rowb)     sc[1] = -1e30f;
                    if (colb     > rowb + 8) sc[2] = -1e30f;
                    if (colb + 1 > rowb + 8) sc[3] = -1e30f;
                }
        }
        float rmax[2][2] = {{-1e30f, -1e30f}, {-1e30f, -1e30f}};
#pragma unroll
        for (int mt = 0; mt < 2; mt++)
#pragma unroll
            for (int nt = 0; nt < 4; nt++) {
                float4 s4 = sacc[mt][nt];
                rmax[mt][0] = fmaxf(rmax[mt][0], fmaxf(s4.x, s4.y));
                rmax[mt][1] = fmaxf(rmax[mt][1], fmaxf(s4.z, s4.w));
            }
#pragma unroll
        for (int mt = 0; mt < 2; mt++)
#pragma unroll
            for (int hf = 0; hf < 2; hf++) {
                float x = rmax[mt][hf];
                x = fmaxf(x, __shfl_xor_sync(0xffffffffu, x, 1));
                x = fmaxf(x, __shfl_xor_sync(0xffffffffu, x, 2));
                rmax[mt][hf] = x;
            }
        if (t == 0) {
#pragma unroll
            for (int mt = 0; mt < 2; mt++)
#pragma unroll
                for (int hf = 0; hf < 2; hf++)
                    sm[MB_OFF + wn * 128 + wm * 32 + mt * 16 + hf * 8 + g] = rmax[mt][hf];
        }
        __syncthreads();   // sync1: MB visible; old V/K buffers free

        // (4) commit V
#pragma unroll
        for (int i = 0; i < 8; i++)
            *(uint4*)&smu[VS_OFF + (i * 8 + ldrow) * 136 + ldc * 4] = cvt4(vreg[i]);

        // (5) stage K(kt+1)
        float4 kreg[8];
        const bool havek = (kt + 1 < ntiles);
        if (havek) {
#pragma unroll
            for (int i = 0; i < 8; i++)
                kreg[i] = k4[((size_t)(b * SQ + k0 + 64 + i * 8 + ldrow) * NKV + kvh) * 32 + ldc];
        }

        // (6) softmax
        float alpha[2][2];
#pragma unroll
        for (int mt = 0; mt < 2; mt++)
#pragma unroll
            for (int hf = 0; hf < 2; hf++) {
                int row = wm * 32 + mt * 16 + hf * 8 + g;
                float mn = fmaxf(m_s[mt][hf],
                                 fmaxf(sm[MB_OFF + row], sm[MB_OFF + 128 + row]));
                alpha[mt][hf] = __expf(m_s[mt][hf] - mn);
                m_s[mt][hf] = mn;
            }
        float rsum[2][2] = {{0.f, 0.f}, {0.f, 0.f}};
#pragma unroll
        for (int mt = 0; mt < 2; mt++)
#pragma unroll
            for (int nt = 0; nt < 4; nt++) {
                float4 s4 = sacc[mt][nt];
                float p0 = __expf(s4.x - m_s[mt][0]);
                float p1 = __expf(s4.y - m_s[mt][0]);
                float p2 = __expf(s4.z - m_s[mt][1]);
                float p3 = __expf(s4.w - m_s[mt][1]);
                rsum[mt][0] += p0 + p1;
                rsum[mt][1] += p2 + p3;
                int cb = wn * 32 + nt * 8 + 2 * t;
                int rl = wm * 32 + mt * 16 + g;
                *(uint2*)&smu[PS_OFF + rl * 68 + cb] =
                    make_uint2(to_tf32(p0), to_tf32(p1));
                *(uint2*)&smu[PS_OFF + (rl + 8) * 68 + cb] =
                    make_uint2(to_tf32(p2), to_tf32(p3));
            }
#pragma unroll
        for (int mt = 0; mt < 2; mt++)
#pragma unroll
            for (int hf = 0; hf < 2; hf++) {
                float x = rsum[mt][hf];
                x += __shfl_xor_sync(0xffffffffu, x, 1);
                x += __shfl_xor_sync(0xffffffffu, x, 2);
                rsum[mt][hf] = x;
            }
        if (t == 0) {
#pragma unroll
            for (int mt = 0; mt < 2; mt++)
#pragma unroll
                for (int hf = 0; hf < 2; hf++)
                    sm[LB_OFF + wn * 128 + wm * 32 + mt * 16 + hf * 8 + g] = rsum[mt][hf];
        }
#pragma unroll
        for (int mt = 0; mt < 2; mt++)
#pragma unroll
            for (int nt = 0; nt < 8; nt++) {
                oacc[mt][nt].x *= alpha[mt][0];
                oacc[mt][nt].y *= alpha[mt][0];
                oacc[mt][nt].z *= alpha[mt][1];
                oacc[mt][nt].w *= alpha[mt][1];
            }

        // (7) commit K(kt+1)
        const int KBn = (kt & 1) ? K0_OFF : K1_OFF;
        if (havek) {
#pragma unroll
            for (int i = 0; i < 8; i++)
                *(uint4*)&smu[KBn + (i * 8 + ldrow) * 132 + ldc * 4] = cvt4(kreg[i]);
        }
        __syncthreads();   // sync2: P, LB, V, K(next) visible

        // (8) l update + O += P @ V
#pragma unroll
        for (int mt = 0; mt < 2; mt++)
#pragma unroll
            for (int hf = 0; hf < 2; hf++) {
                int row = wm * 32 + mt * 16 + hf * 8 + g;
                l_s[mt][hf] = l_s[mt][hf] * alpha[mt][hf]
                            + sm[LB_OFF + row] + sm[LB_OFF + 128 + row];
            }
#pragma unroll
        for (int ks = 0; ks < 8; ks++) {
            const int c0 = ks * 8 + t;
            uint32_t af[2][4];
#pragma unroll
            for (int mt = 0; mt < 2; mt++) {
                int rb = PS_OFF + (r0 + mt * 16) * 68 + c0;
                af[mt][0] = smu[rb];
                af[mt][1] = smu[rb + 68 * 8];
                af[mt][2] = smu[rb + 4];
                af[mt][3] = smu[rb + 68 * 8 + 4];
            }
#pragma unroll
            for (int nt = 0; nt < 8; nt++) {
                int nb = VS_OFF + c0 * 136 + wn * 64 + nt * 8 + g;
                uint2 bf = make_uint2(smu[nb], smu[nb + 4 * 136]);
                mma168(oacc[0][nt], af[0], bf);
                mma168(oacc[1][nt], af[1], bf);
            }
        }
    }

    // ---- epilogue ----
#pragma unroll
    for (int mt = 0; mt < 2; mt++) {
        float i0 = 1.f / l_s[mt][0], i1 = 1.f / l_s[mt][1];
#pragma unroll
        for (int nt = 0; nt < 8; nt++) {
            int row = q0 + wm * 32 + mt * 16 + g;
            int col = h * HD + wn * 64 + nt * 8 + 2 * t;
            float4 o = oacc[mt][nt];
            *(float2*)&out[(size_t)(b * SQ + row) * EB + col] =
                make_float2(o.x * i0, o.y * i0);
            *(float2*)&out[(size_t)(b * SQ + row + 8) * EB + col] =
                make_float2(o.z * i1, o.w * i1);
        }
    }
}

// ---------------------------------------------------------------------------
extern "C" void kernel_launch(void* const* d_in, const int* in_sizes, int n_in,
                              void* d_out, int out_size)
{
    const float* x  = (const float*)d_in[0];
    const float* Wq = (const float*)d_in[1];
    const float* Wk = (const float*)d_in[2];
    const float* Wv = (const float*)d_in[3];
    const float* Wo = (const float*)d_in[4];

    float *qb, *kb, *vb, *ab, *wt;
    cudaGetSymbolAddress((void**)&qb, g_q);
    cudaGetSymbolAddress((void**)&kb, g_k);
    cudaGetSymbolAddress((void**)&vb, g_v);
    cudaGetSymbolAddress((void**)&ab, g_attn);
    cudaGetSymbolAddress((void**)&wt, g_wt);

    const int M = BATCH * SQ;   // 4096

    cudaFuncSetAttribute(gemm_mma, cudaFuncAttributeMaxDynamicSharedMemorySize,
                         GEMM_SMEM);
    cudaFuncSetAttribute(attn_mma, cudaFuncAttributeMaxDynamicSharedMemorySize,
                         ATT_SMEM);

    // Pack Q|K|V weights into one fragment buffer (np blocks of 128 cols)
    pack_b<<<(EB * EB / 2 + 255) / 256, 256>>>(Wq, wt, EB, EB);
    pack_b<<<(EB * KVDIM / 2 + 255) / 256, 256>>>(Wk, wt + 16 * 262144, EB, KVDIM);
    pack_b<<<(EB * KVDIM / 2 + 255) / 256, 256>>>(Wv, wt + 20 * 262144, EB, KVDIM);

    // Fused QKV projection: N = 2048 + 512 + 512 = 3072
    gemm_mma<<<dim3(3072 / 128, M / 256), 512, GEMM_SMEM>>>(
        x, wt, qb, kb, vb, M, 3072, EB, 1);

    // RoPE (+ q scaling)
    int npairs = BATCH * SQ * (NH + NKV) * 64;
    rope_kernel<<<(npairs + 255) / 256, 256>>>(qb, kb);

    // Tensor-core flash attention
    attn_mma<<<dim3(SQ / 128, NH, BATCH), 256, ATT_SMEM>>>(qb, kb, vb, ab);

    // Output projection
    pack_b<<<(EB * EB / 2 + 255) / 256, 256>>>(Wo, wt, EB, EB);
    gemm_mma<<<dim3(EB / 128, M / 256), 512, GEMM_SMEM>>>(
        ab, wt, (float*)d_out, nullptr, nullptr, M, EB, EB, 0);
}

// round 8
// speedup vs baseline: 1.5882x; 1.5882x over previous
#include <cuda_runtime.h>
#include <cuda_fp16.h>
#include <cstdint>

#define SQ    2048
#define EB    2048
#define BATCH 2
#define NH    16
#define NKV   4
#define HD    128
#define KVDIM (NKV*HD)

// Scratch (device globals — allocation inside kernel_launch is forbidden)
__device__ float  g_q[BATCH * SQ * NH * HD];      // 32 MB (fp32 QKV gemm out)
__device__ float  g_k[BATCH * SQ * NKV * HD];     //  8 MB
__device__ float  g_v[BATCH * SQ * NKV * HD];     //  8 MB
__device__ __half g_xh[BATCH * SQ * EB];          // 16 MB (x in fp16)
__device__ __half g_qh[BATCH * SQ * NH * HD];     // 16 MB (roped q fp16)
__device__ __half g_kh[BATCH * SQ * NKV * HD];    //  4 MB (roped k fp16)
__device__ __half g_vth[BATCH * NKV * HD * SQ];   //  4 MB (v transposed fp16)
__device__ __half g_ah[BATCH * SQ * EB];          // 16 MB (attn out fp16)
__device__ __half g_wh[EB * 3072];                // 12.6 MB (packed weights fp16)

// ---------------------------------------------------------------------------
__device__ __forceinline__ uint32_t smem_u32(const void* p) {
    uint32_t a;
    asm("{ .reg .u64 t; cvta.to.shared.u64 t, %1; cvt.u32.u64 %0, t; }"
        : "=r"(a) : "l"(p));
    return a;
}

__device__ __forceinline__ uint32_t packh2(float a, float b) {
    __half2 h = __floats2half2_rn(a, b);
    return *(uint32_t*)&h;
}

__device__ __forceinline__ void cp_async16(uint32_t smem_addr, const void* gptr) {
    asm volatile("cp.async.cg.shared.global [%0], [%1], 16;"
                 :: "r"(smem_addr), "l"(gptr));
}

// fp16 m16n8k16, fp32 accumulate
__device__ __forceinline__ void mma16816(float4& d, const uint32_t* a, uint2 b) {
    asm volatile(
        "mma.sync.aligned.m16n8k16.row.col.f32.f16.f16.f32 "
        "{%0,%1,%2,%3}, {%4,%5,%6,%7}, {%8,%9}, {%0,%1,%2,%3};"
        : "+f"(d.x), "+f"(d.y), "+f"(d.z), "+f"(d.w)
        : "r"(a[0]), "r"(a[1]), "r"(a[2]), "r"(a[3]), "r"(b.x), "r"(b.y));
}

// ---------------------------------------------------------------------------
// x (fp32) -> fp16
// ---------------------------------------------------------------------------
__global__ void cvt_x(const float* __restrict__ x, __half* __restrict__ xh, int n4)
{
    int i = blockIdx.x * blockDim.x + threadIdx.x;
    if (i >= n4) return;
    float4 v = ((const float4*)x)[i];
    uint2 o = make_uint2(packh2(v.x, v.y), packh2(v.z, v.w));
    ((uint2*)xh)[i] = o;
}

// ---------------------------------------------------------------------------
// Pack W[k][n] (KxN fp32 row-major) into fp16 m16n8k16 B-fragment order.
// word gid: j=gid&1, lane=(gid>>1)&31, kh=(gid>>6)&1, nt=(gid>>7)&15,
//           kc=(gid>>11)%KC, np=(gid>>11)/KC
// n = np*128+nt*8+(lane>>2);  k = kc*32+kh*16+(lane&3)*2+j*8
// word = {W[k][n], W[k+1][n]}
// ---------------------------------------------------------------------------
__global__ void pack_bh(const float* __restrict__ W, __half* __restrict__ Bp,
                        int K, int N)
{
    int gid = blockIdx.x * blockDim.x + threadIdx.x;
    int total = (K * N) >> 1;
    if (gid >= total) return;
    const int KC = K / 32;
    int j    = gid & 1;
    int lane = (gid >> 1) & 31;
    int kh   = (gid >> 6) & 1;
    int nt   = (gid >> 7) & 15;
    int kc   = (gid >> 11) % KC;
    int np   = (gid >> 11) / KC;
    int n = np * 128 + nt * 8 + (lane >> 2);
    int k = kc * 32 + kh * 16 + (lane & 3) * 2 + j * 8;
    ((uint32_t*)Bp)[gid] = packh2(W[(size_t)k * N + n], W[(size_t)(k + 1) * N + n]);
}

// ---------------------------------------------------------------------------
// FP16 GEMM: C[M,N] = A[M,K] @ B[K,N], A fp16 row-major, B fragment-packed.
// CTA 256x128, 512 thr = 16 warps (wm 4 x wn 4), warp tile 64x32.
// 4-stage cp.async. A smem rows padded to 40 halves (20 words, conflict-free).
// Stage = A 20480 B + B 8192 B = 28672 B.
// ---------------------------------------------------------------------------
#define GEMM_SMEM 114688
#define GSTW 7168   // stage stride in words

__device__ __forceinline__ void gemm_issue_h(
    const __half* __restrict__ A, const __half* __restrict__ Bp,
    uint32_t sb, int c, int tm0, int np, int K, int KC, int tid)
{
    const uint32_t base = sb + (c & 3) * 28672;
#pragma unroll
    for (int i = 0; i < 2; i++) {
        int f = i * 512 + tid;
        int row = f >> 2, gc = f & 3;
        cp_async16(base + row * 80 + gc * 16,
                   A + (size_t)(tm0 + row) * K + c * 32 + gc * 8);
    }
    cp_async16(base + 20480 + tid * 16,
               Bp + ((size_t)np * KC + c) * 4096 + tid * 8);
    asm volatile("cp.async.commit_group;" ::: "memory");
}

__global__ __launch_bounds__(512, 1) void gemm_h(
    const __half* __restrict__ A, const __half* __restrict__ Bp,
    float* __restrict__ C0, float* __restrict__ C1, float* __restrict__ C2,
    int M, int N, int K, int fused)
{
    extern __shared__ float sm[];
    uint32_t* smw = (uint32_t*)sm;
    const int tid = threadIdx.x;
    const int lane = tid & 31, wid = tid >> 5;
    const int g = lane >> 2, t = lane & 3;
    const int wm = wid & 3, wn = wid >> 2;
    const int tm0 = blockIdx.y * 256, tn0 = blockIdx.x * 128;
    const int np = blockIdx.x;
    const int KC = K / 32;
    const uint32_t sb = smem_u32(sm);

    float4 acc[4][4];
#pragma unroll
    for (int i = 0; i < 4; i++)
#pragma unroll
        for (int j = 0; j < 4; j++) acc[i][j] = make_float4(0.f, 0.f, 0.f, 0.f);

    gemm_issue_h(A, Bp, sb, 0, tm0, np, K, KC, tid);
    gemm_issue_h(A, Bp, sb, 1, tm0, np, K, KC, tid);
    gemm_issue_h(A, Bp, sb, 2, tm0, np, K, KC, tid);

    const int r0 = wm * 64 + g;

    for (int c = 0; c < KC; c++) {
        const int rem = KC - 1 - c;
        if (rem >= 2)      asm volatile("cp.async.wait_group 2;" ::: "memory");
        else if (rem == 1) asm volatile("cp.async.wait_group 1;" ::: "memory");
        else               asm volatile("cp.async.wait_group 0;" ::: "memory");
        __syncthreads();

        const uint32_t* As = smw + (c & 3) * GSTW;        // A: 256 rows x 20 words
        const uint32_t* Bs = As + 5120;                   // B: 2048 words

#pragma unroll
        for (int kh = 0; kh < 2; kh++) {
            uint32_t af[4][4];
#pragma unroll
            for (int mt = 0; mt < 4; mt++) {
                const int rb = (r0 + mt * 16) * 20 + kh * 8 + t;
                af[mt][0] = As[rb];
                af[mt][1] = As[rb + 8 * 20];
                af[mt][2] = As[rb + 4];
                af[mt][3] = As[rb + 8 * 20 + 4];
            }
#pragma unroll
            for (int nt = 0; nt < 4; nt++) {
                uint2 bf = *(const uint2*)&Bs[(((wn * 4 + nt) * 2 + kh) * 32 + lane) * 2];
                mma16816(acc[0][nt], af[0], bf);
                mma16816(acc[1][nt], af[1], bf);
                mma16816(acc[2][nt], af[2], bf);
                mma16816(acc[3][nt], af[3], bf);
            }
        }

        if (c + 3 < KC)
            gemm_issue_h(A, Bp, sb, c + 3, tm0, np, K, KC, tid);
    }

    float* Cd; int ldc, coff;
    if (!fused)            { Cd = C0; ldc = N;    coff = 0;    }
    else if (tn0 < 2048)   { Cd = C0; ldc = 2048; coff = 0;    }
    else if (tn0 < 2560)   { Cd = C1; ldc = 512;  coff = 2048; }
    else                   { Cd = C2; ldc = 512;  coff = 2560; }

#pragma unroll
    for (int mt = 0; mt < 4; mt++) {
#pragma unroll
        for (int nt = 0; nt < 4; nt++) {
            int row = tm0 + wm * 64 + mt * 16 + g;
            int col = tn0 + wn * 32 + nt * 8 + t * 2 - coff;
            float4 a = acc[mt][nt];
            *(float2*)&Cd[(size_t)row * ldc + col] = make_float2(a.x, a.y);
            *(float2*)&Cd[(size_t)(row + 8) * ldc + col] = make_float2(a.z, a.w);
        }
    }
}

// ---------------------------------------------------------------------------
// RoPE: reads fp32 q/k, writes fp16 (q scaled by 1/sqrt(HD)).
// ---------------------------------------------------------------------------
__global__ void rope_h(const float* __restrict__ q, const float* __restrict__ k,
                       __half* __restrict__ qh, __half* __restrict__ kh)
{
    const int NQ = BATCH * SQ * NH * 64;
    const int NK = BATCH * SQ * NKV * 64;
    int i = blockIdx.x * blockDim.x + threadIdx.x;
    if (i >= NQ + NK) return;

    const float* src;
    __half* dst;
    int d, s;
    float scale;
    if (i < NQ) {
        d = i & 63;
        int rest = i >> 6;
        s = (rest >> 4) & (SQ - 1);
        src = q + (size_t)rest * HD;
        dst = qh + (size_t)rest * HD;
        scale = 0.08838834764831845f;
    } else {
        int j = i - NQ;
        d = j & 63;
        int rest = j >> 6;
        s = (rest >> 2) & (SQ - 1);
        src = k + (size_t)rest * HD;
        dst = kh + (size_t)rest * HD;
        scale = 1.0f;
    }
    float inv_freq = powf(10000.0f, -(float)d * (1.0f / 64.0f));
    float ang = (float)s * inv_freq;
    float c = cosf(ang), sn = sinf(ang);
    float a = src[d], b = src[d + 64];
    dst[d]      = __float2half((a * c - b * sn) * scale);
    dst[d + 64] = __float2half((b * c + a * sn) * scale);
}

// ---------------------------------------------------------------------------
// V transpose: v fp32 [B,S,NKV,HD] -> vt fp16 [B,NKV,HD,SQ]
// ---------------------------------------------------------------------------
__global__ void vt_kernel(const float* __restrict__ v, __half* __restrict__ vt)
{
    __shared__ float tile[32][33];
    const int s0 = blockIdx.x * 32, d0 = blockIdx.y * 32;
    const int bk = blockIdx.z;              // b*NKV + kvh
    const int x = threadIdx.x, y = threadIdx.y;   // 32 x 8
#pragma unroll
    for (int i = 0; i < 32; i += 8)
        tile[y + i][x] = v[((size_t)(blockIdx.z / NKV * SQ + s0 + y + i) * NKV
                            + (bk % NKV)) * HD + d0 + x];
    __syncthreads();
#pragma unroll
    for (int i = 0; i < 32; i += 8)
        vt[((size_t)bk * HD + d0 + y + i) * SQ + s0 + x] =
            __float2half(tile[x][y + i]);
}

// ---------------------------------------------------------------------------
// FP16 tensor-core flash attention. Same skeleton as the passing tf32 version.
// CTA = 128 q rows x (b,h); 8 warps (wm rows, wn halves). K double-buffered,
// V^T + next-K register-staged. Word-strides: Q/K 68, P/Vt 36 (conflict-free).
// Word offsets: QS 0, K0 8704, K1 13056, VT 17408, PS 22016, MB 26624, LB 26880.
// ---------------------------------------------------------------------------
#define AQS 0
#define AK0 8704
#define AK1 13056
#define AVT 17408
#define APS 22016
#define AMB 26624
#define ALB 26880
#define ATT_SMEM (27136 * 4)

__global__ __launch_bounds__(256, 1) void attn_h(
    const __half* __restrict__ qh, const __half* __restrict__ kh,
    const __half* __restrict__ vth, __half* __restrict__ outh)
{
    extern __shared__ float sm[];
    uint32_t* smw = (uint32_t*)sm;
    const int tid = threadIdx.x;
    const int lane = tid & 31, wid = tid >> 5;
    const int g = lane >> 2, t = lane & 3;
    const int wm = wid & 3, wn = wid >> 2;
    const int qt = gridDim.x - 1 - blockIdx.x;   // LPT
    const int h = blockIdx.y, b = blockIdx.z;
    const int kvh = h >> 2;
    const int q0 = qt * 128;

    const uint4* q16 = (const uint4*)qh;     // 8 halves per uint4
    const uint4* k16 = (const uint4*)kh;
    const uint4* vt16 = (const uint4*)vth;

    // ---- prologue: Q tile + K tile 0 ----
#pragma unroll
    for (int i = 0; i < 8; i++) {
        int f = i * 256 + tid;
        int row = f >> 4, c = f & 15;
        uint4 v = q16[((size_t)(b * SQ + q0 + row) * NH + h) * 16 + c];
        *(uint4*)&smw[AQS + row * 68 + c * 4] = v;
    }
    {
        int row = tid >> 2, qd = tid & 3;    // 64 rows x 4 uint4
#pragma unroll
        for (int i = 0; i < 4; i++) {
            uint4 v = k16[((size_t)(b * SQ + row) * NKV + kvh) * 16 + qd * 4 + i];
            *(uint4*)&smw[AK0 + row * 68 + qd * 16 + i * 4] = v;
        }
    }
    __syncthreads();

    float4 oacc[2][8];
#pragma unroll
    for (int i = 0; i < 2; i++)
#pragma unroll
        for (int j = 0; j < 8; j++) oacc[i][j] = make_float4(0.f, 0.f, 0.f, 0.f);
    float m_s[2][2] = {{-1e30f, -1e30f}, {-1e30f, -1e30f}};
    float l_s[2][2] = {{0.f, 0.f}, {0.f, 0.f}};

    const int r0 = wm * 32 + g;
    const int ntiles = 2 * qt + 2;
    const int vrow = tid >> 1, vhalf = tid & 1;   // Vt: 128 d x 8 uint4
    const int krow = tid >> 2, kq = tid & 3;      // K:  64 rows x 4 uint4

    for (int kt = 0; kt < ntiles; kt++) {
        const int k0 = kt * 64;
        const int KB = (kt & 1) ? AK1 : AK0;

        // (1) stage Vt(kt): rows=d(128), cols = 32 words (64 keys)
        uint4 vreg[4];
        {
            size_t base = (((size_t)(b * NKV + kvh) * HD + vrow) * SQ + k0) >> 3;
#pragma unroll
            for (int i = 0; i < 4; i++)
                vreg[i] = vt16[base + vhalf * 4 + i];
        }

        // (2) S = Q @ K^T   (8 k16 steps over HD=128)
        float4 sacc[2][4];
#pragma unroll
        for (int i = 0; i < 2; i++)
#pragma unroll
            for (int j = 0; j < 4; j++) sacc[i][j] = make_float4(0.f, 0.f, 0.f, 0.f);
#pragma unroll
        for (int ks = 0; ks < 8; ks++) {
            const int c0 = ks * 8 + t;
            uint32_t af[2][4];
#pragma unroll
            for (int mt = 0; mt < 2; mt++) {
                int rb = AQS + (r0 + mt * 16) * 68 + c0;
                af[mt][0] = smw[rb];
                af[mt][1] = smw[rb + 68 * 8];
                af[mt][2] = smw[rb + 4];
                af[mt][3] = smw[rb + 68 * 8 + 4];
            }
#pragma unroll
            for (int nt = 0; nt < 4; nt++) {
                int nb = KB + (wn * 32 + nt * 8 + g) * 68 + c0;
                uint2 bf = make_uint2(smw[nb], smw[nb + 4]);
                mma16816(sacc[0][nt], af[0], bf);
                mma16816(sacc[1][nt], af[1], bf);
            }
        }

        // (3) causal mask + row max
        if (kt >= 2 * qt) {
#pragma unroll
            for (int mt = 0; mt < 2; mt++)
#pragma unroll
                for (int nt = 0; nt < 4; nt++) {
                    int colb = k0 + wn * 32 + nt * 8 + 2 * t;
                    int rowb = q0 + wm * 32 + mt * 16 + g;
                    float* sc = (float*)&sacc[mt][nt];
                    if (colb     > rowb)     sc[0] = -1e30f;
                    if (colb + 1 > rowb)     sc[1] = -1e30f;
                    if (colb     > rowb + 8) sc[2] = -1e30f;
                    if (colb + 1 > rowb + 8) sc[3] = -1e30f;
                }
        }
        float rmax[2][2] = {{-1e30f, -1e30f}, {-1e30f, -1e30f}};
#pragma unroll
        for (int mt = 0; mt < 2; mt++)
#pragma unroll
            for (int nt = 0; nt < 4; nt++) {
                float4 s4 = sacc[mt][nt];
                rmax[mt][0] = fmaxf(rmax[mt][0], fmaxf(s4.x, s4.y));
                rmax[mt][1] = fmaxf(rmax[mt][1], fmaxf(s4.z, s4.w));
            }
#pragma unroll
        for (int mt = 0; mt < 2; mt++)
#pragma unroll
            for (int hf = 0; hf < 2; hf++) {
                float x = rmax[mt][hf];
                x = fmaxf(x, __shfl_xor_sync(0xffffffffu, x, 1));
                x = fmaxf(x, __shfl_xor_sync(0xffffffffu, x, 2));
                rmax[mt][hf] = x;
            }
        if (t == 0) {
#pragma unroll
            for (int mt = 0; mt < 2; mt++)
#pragma unroll
                for (int hf = 0; hf < 2; hf++)
                    sm[AMB + wn * 128 + wm * 32 + mt * 16 + hf * 8 + g] = rmax[mt][hf];
        }
        __syncthreads();   // sync1

        // (4) commit Vt
#pragma unroll
        for (int i = 0; i < 4; i++)
            *(uint4*)&smw[AVT + vrow * 36 + vhalf * 16 + i * 4] = vreg[i];

        // (5) stage K(kt+1)
        uint4 kreg[4];
        const bool havek = (kt + 1 < ntiles);
        if (havek) {
#pragma unroll
            for (int i = 0; i < 4; i++)
                kreg[i] = k16[((size_t)(b * SQ + k0 + 64 + krow) * NKV + kvh) * 16 + kq * 4 + i];
        }

        // (6) softmax
        float alpha[2][2];
#pragma unroll
        for (int mt = 0; mt < 2; mt++)
#pragma unroll
            for (int hf = 0; hf < 2; hf++) {
                int row = wm * 32 + mt * 16 + hf * 8 + g;
                float mn = fmaxf(m_s[mt][hf],
                                 fmaxf(sm[AMB + row], sm[AMB + 128 + row]));
                alpha[mt][hf] = __expf(m_s[mt][hf] - mn);
                m_s[mt][hf] = mn;
            }
        float rsum[2][2] = {{0.f, 0.f}, {0.f, 0.f}};
#pragma unroll
        for (int mt = 0; mt < 2; mt++)
#pragma unroll
            for (int nt = 0; nt < 4; nt++) {
                float4 s4 = sacc[mt][nt];
                float p0 = __expf(s4.x - m_s[mt][0]);
                float p1 = __expf(s4.y - m_s[mt][0]);
                float p2 = __expf(s4.z - m_s[mt][1]);
                float p3 = __expf(s4.w - m_s[mt][1]);
                rsum[mt][0] += p0 + p1;
                rsum[mt][1] += p2 + p3;
                int cw = wn * 16 + nt * 4 + t;
                int rl = wm * 32 + mt * 16 + g;
                smw[APS + rl * 36 + cw]       = packh2(p0, p1);
                smw[APS + (rl + 8) * 36 + cw] = packh2(p2, p3);
            }
#pragma unroll
        for (int mt = 0; mt < 2; mt++)
#pragma unroll
            for (int hf = 0; hf < 2; hf++) {
                float x = rsum[mt][hf];
                x += __shfl_xor_sync(0xffffffffu, x, 1);
                x += __shfl_xor_sync(0xffffffffu, x, 2);
                rsum[mt][hf] = x;
            }
        if (t == 0) {
#pragma unroll
            for (int mt = 0; mt < 2; mt++)
#pragma unroll
                for (int hf = 0; hf < 2; hf++)
                    sm[ALB + wn * 128 + wm * 32 + mt * 16 + hf * 8 + g] = rsum[mt][hf];
        }
#pragma unroll
        for (int mt = 0; mt < 2; mt++)
#pragma unroll
            for (int nt = 0; nt < 8; nt++) {
                oacc[mt][nt].x *= alpha[mt][0];
                oacc[mt][nt].y *= alpha[mt][0];
                oacc[mt][nt].z *= alpha[mt][1];
                oacc[mt][nt].w *= alpha[mt][1];
            }

        // (7) commit K(kt+1)
        const int KBn = (kt & 1) ? AK0 : AK1;
        if (havek) {
#pragma unroll
            for (int i = 0; i < 4; i++)
                *(uint4*)&smw[KBn + krow * 68 + kq * 16 + i * 4] = kreg[i];
        }
        __syncthreads();   // sync2

        // (8) l update + O += P @ V  (4 k16 steps over 64 keys)
#pragma unroll
        for (int mt = 0; mt < 2; mt++)
#pragma unroll
            for (int hf = 0; hf < 2; hf++) {
                int row = wm * 32 + mt * 16 + hf * 8 + g;
                l_s[mt][hf] = l_s[mt][hf] * alpha[mt][hf]
                            + sm[ALB + row] + sm[ALB + 128 + row];
            }
#pragma unroll
        for (int ks = 0; ks < 4; ks++) {
            const int c0 = ks * 8 + t;
            uint32_t af[2][4];
#pragma unroll
            for (int mt = 0; mt < 2; mt++) {
                int rb = APS + (r0 + mt * 16) * 36 + c0;
                af[mt][0] = smw[rb];
                af[mt][1] = smw[rb + 36 * 8];
                af[mt][2] = smw[rb + 4];
                af[mt][3] = smw[rb + 36 * 8 + 4];
            }
#pragma unroll
            for (int nt = 0; nt < 8; nt++) {
                int nb = AVT + (wn * 64 + nt * 8 + g) * 36 + c0;
                uint2 bf = make_uint2(smw[nb], smw[nb + 4]);
                mma16816(oacc[0][nt], af[0], bf);
                mma16816(oacc[1][nt], af[1], bf);
            }
        }
    }

    // ---- epilogue: fp16 out for O-projection A operand ----
    uint32_t* outw = (uint32_t*)outh;
#pragma unroll
    for (int mt = 0; mt < 2; mt++) {
        float i0 = 1.f / l_s[mt][0], i1 = 1.f / l_s[mt][1];
#pragma unroll
        for (int nt = 0; nt < 8; nt++) {
            int row = q0 + wm * 32 + mt * 16 + g;
            int cw = h * 64 + wn * 32 + nt * 4 + t;
            float4 o = oacc[mt][nt];
            outw[(size_t)(b * SQ + row) * 1024 + cw]     = packh2(o.x * i0, o.y * i0);
            outw[(size_t)(b * SQ + row + 8) * 1024 + cw] = packh2(o.z * i1, o.w * i1);
        }
    }
}

// ---------------------------------------------------------------------------
extern "C" void kernel_launch(void* const* d_in, const int* in_sizes, int n_in,
                              void* d_out, int out_size)
{
    const float* x  = (const float*)d_in[0];
    const float* Wq = (const float*)d_in[1];
    const float* Wk = (const float*)d_in[2];
    const float* Wv = (const float*)d_in[3];
    const float* Wo = (const float*)d_in[4];

    float *qb, *kb, *vb;
    __half *xh, *qh, *kh, *vth, *ah, *wh;
    cudaGetSymbolAddress((void**)&qb, g_q);
    cudaGetSymbolAddress((void**)&kb, g_k);
    cudaGetSymbolAddress((void**)&vb, g_v);
    cudaGetSymbolAddress((void**)&xh, g_xh);
    cudaGetSymbolAddress((void**)&qh, g_qh);
    cudaGetSymbolAddress((void**)&kh, g_kh);
    cudaGetSymbolAddress((void**)&vth, g_vth);
    cudaGetSymbolAddress((void**)&ah, g_ah);
    cudaGetSymbolAddress((void**)&wh, g_wh);

    const int M = BATCH * SQ;   // 4096

    cudaFuncSetAttribute(gemm_h, cudaFuncAttributeMaxDynamicSharedMemorySize,
                         GEMM_SMEM);
    cudaFuncSetAttribute(attn_h, cudaFuncAttributeMaxDynamicSharedMemorySize,
                         ATT_SMEM);

    // x -> fp16
    cvt_x<<<(M * EB / 4 + 255) / 256, 256>>>(x, xh, M * EB / 4);

    // Pack Q|K|V weights (fp16 fragments); np-block offsets match fused N=3072
    pack_bh<<<(EB * EB / 2 + 255) / 256, 256>>>(Wq, wh, EB, EB);
    pack_bh<<<(EB * KVDIM / 2 + 255) / 256, 256>>>(Wk, wh + 16 * 262144, EB, KVDIM);
    pack_bh<<<(EB * KVDIM / 2 + 255) / 256, 256>>>(Wv, wh + 20 * 262144, EB, KVDIM);

    // Fused QKV projection (fp32 out)
    gemm_h<<<dim3(3072 / 128, M / 256), 512, GEMM_SMEM>>>(
        xh, wh, qb, kb, vb, M, 3072, EB, 1);

    // RoPE -> fp16 q/k ; V -> fp16 transposed
    int npairs = BATCH * SQ * (NH + NKV) * 64;
    rope_h<<<(npairs + 255) / 256, 256>>>(qb, kb, qh, kh);
    vt_kernel<<<dim3(SQ / 32, HD / 32, BATCH * NKV), dim3(32, 8)>>>(vb, vth);

    // FP16 flash attention -> fp16 attn output
    attn_h<<<dim3(SQ / 128, NH, BATCH), 256, ATT_SMEM>>>(qh, kh, vth, ah);

    // Output projection (fp16 A, fp32 out)
    pack_bh<<<(EB * EB / 2 + 255) / 256, 256>>>(Wo, wh, EB, EB);
    gemm_h<<<dim3(EB / 128, M / 256), 512, GEMM_SMEM>>>(
        ah, wh, (float*)d_out, nullptr, nullptr, M, EB, EB, 0);
}

// round 9
// speedup vs baseline: 1.6103x; 1.0139x over previous
#include <cuda_runtime.h>
#include <cuda_fp16.h>
#include <cstdint>

#define SQ    2048
#define EB    2048
#define BATCH 2
#define NH    16
#define NKV   4
#define HD    128
#define KVDIM (NKV*HD)

// Scratch (device globals — allocation inside kernel_launch is forbidden)
__device__ __half g_xh[BATCH * SQ * EB];          // x fp16
__device__ __half g_qh[BATCH * SQ * NH * HD];     // q fp16 (gemm out, roped in place)
__device__ __half g_kh[BATCH * SQ * NKV * HD];    // k fp16 (gemm out, roped in place)
__device__ __half g_vh[BATCH * SQ * NKV * HD];    // v fp16 (gemm out)
__device__ __half g_vth[BATCH * NKV * HD * SQ];   // v transposed fp16
__device__ __half g_ah[BATCH * SQ * EB];          // attn out fp16
__device__ __half g_wh[EB * 3072];                // packed weights fp16

// ---------------------------------------------------------------------------
__device__ __forceinline__ uint32_t smem_u32(const void* p) {
    uint32_t a;
    asm("{ .reg .u64 t; cvta.to.shared.u64 t, %1; cvt.u32.u64 %0, t; }"
        : "=r"(a) : "l"(p));
    return a;
}

__device__ __forceinline__ uint32_t packh2(float a, float b) {
    __half2 h = __floats2half2_rn(a, b);
    return *(uint32_t*)&h;
}

__device__ __forceinline__ void cp_async16(uint32_t smem_addr, const void* gptr) {
    asm volatile("cp.async.cg.shared.global [%0], [%1], 16;"
                 :: "r"(smem_addr), "l"(gptr));
}

__device__ __forceinline__ void mma16816(float4& d, const uint32_t* a, uint2 b) {
    asm volatile(
        "mma.sync.aligned.m16n8k16.row.col.f32.f16.f16.f32 "
        "{%0,%1,%2,%3}, {%4,%5,%6,%7}, {%8,%9}, {%0,%1,%2,%3};"
        : "+f"(d.x), "+f"(d.y), "+f"(d.z), "+f"(d.w)
        : "r"(a[0]), "r"(a[1]), "r"(a[2]), "r"(a[3]), "r"(b.x), "r"(b.y));
}

// ---------------------------------------------------------------------------
__global__ void cvt_x(const float* __restrict__ x, __half* __restrict__ xh, int n4)
{
    int i = blockIdx.x * blockDim.x + threadIdx.x;
    if (i >= n4) return;
    float4 v = ((const float4*)x)[i];
    ((uint2*)xh)[i] = make_uint2(packh2(v.x, v.y), packh2(v.z, v.w));
}

// ---------------------------------------------------------------------------
// Pack W[k][n] (KxN fp32 row-major) into fp16 m16n8k16 B-fragment order.
// ---------------------------------------------------------------------------
__global__ void pack_bh(const float* __restrict__ W, __half* __restrict__ Bp,
                        int K, int N)
{
    int gid = blockIdx.x * blockDim.x + threadIdx.x;
    int total = (K * N) >> 1;
    if (gid >= total) return;
    const int KC = K / 32;
    int j    = gid & 1;
    int lane = (gid >> 1) & 31;
    int kh   = (gid >> 6) & 1;
    int nt   = (gid >> 7) & 15;
    int kc   = (gid >> 11) % KC;
    int np   = (gid >> 11) / KC;
    int n = np * 128 + nt * 8 + (lane >> 2);
    int k = kc * 32 + kh * 16 + (lane & 3) * 2 + j * 8;
    ((uint32_t*)Bp)[gid] = packh2(W[(size_t)k * N + n], W[(size_t)(k + 1) * N + n]);
}

// ---------------------------------------------------------------------------
// FP16 GEMM: CTA 256x128, 512 thr, warp tile 64x32, 4-stage cp.async.
// half_out: write fp16 (QKV path); else fp32 (O-proj).
// ---------------------------------------------------------------------------
#define GEMM_SMEM 114688
#define GSTW 7168

__device__ __forceinline__ void gemm_issue_h(
    const __half* __restrict__ A, const __half* __restrict__ Bp,
    uint32_t sb, int c, int tm0, int np, int K, int KC, int tid)
{
    const uint32_t base = sb + (c & 3) * 28672;
#pragma unroll
    for (int i = 0; i < 2; i++) {
        int f = i * 512 + tid;
        int row = f >> 2, gc = f & 3;
        cp_async16(base + row * 80 + gc * 16,
                   A + (size_t)(tm0 + row) * K + c * 32 + gc * 8);
    }
    cp_async16(base + 20480 + tid * 16,
               Bp + ((size_t)np * KC + c) * 4096 + tid * 8);
    asm volatile("cp.async.commit_group;" ::: "memory");
}

__global__ __launch_bounds__(512, 1) void gemm_h(
    const __half* __restrict__ A, const __half* __restrict__ Bp,
    void* __restrict__ C0, void* __restrict__ C1, void* __restrict__ C2,
    int M, int N, int K, int fused, int half_out)
{
    extern __shared__ float sm[];
    uint32_t* smw = (uint32_t*)sm;
    const int tid = threadIdx.x;
    const int lane = tid & 31, wid = tid >> 5;
    const int g = lane >> 2, t = lane & 3;
    const int wm = wid & 3, wn = wid >> 2;
    const int tm0 = blockIdx.y * 256, tn0 = blockIdx.x * 128;
    const int np = blockIdx.x;
    const int KC = K / 32;
    const uint32_t sb = smem_u32(sm);

    float4 acc[4][4];
#pragma unroll
    for (int i = 0; i < 4; i++)
#pragma unroll
        for (int j = 0; j < 4; j++) acc[i][j] = make_float4(0.f, 0.f, 0.f, 0.f);

    gemm_issue_h(A, Bp, sb, 0, tm0, np, K, KC, tid);
    gemm_issue_h(A, Bp, sb, 1, tm0, np, K, KC, tid);
    gemm_issue_h(A, Bp, sb, 2, tm0, np, K, KC, tid);

    const int r0 = wm * 64 + g;

    for (int c = 0; c < KC; c++) {
        const int rem = KC - 1 - c;
        if (rem >= 2)      asm volatile("cp.async.wait_group 2;" ::: "memory");
        else if (rem == 1) asm volatile("cp.async.wait_group 1;" ::: "memory");
        else               asm volatile("cp.async.wait_group 0;" ::: "memory");
        __syncthreads();

        const uint32_t* As = smw + (c & 3) * GSTW;
        const uint32_t* Bs = As + 5120;

#pragma unroll
        for (int kh = 0; kh < 2; kh++) {
            uint32_t af[4][4];
#pragma unroll
            for (int mt = 0; mt < 4; mt++) {
                const int rb = (r0 + mt * 16) * 20 + kh * 8 + t;
                af[mt][0] = As[rb];
                af[mt][1] = As[rb + 8 * 20];
                af[mt][2] = As[rb + 4];
                af[mt][3] = As[rb + 8 * 20 + 4];
            }
#pragma unroll
            for (int nt = 0; nt < 4; nt++) {
                uint2 bf = *(const uint2*)&Bs[(((wn * 4 + nt) * 2 + kh) * 32 + lane) * 2];
                mma16816(acc[0][nt], af[0], bf);
                mma16816(acc[1][nt], af[1], bf);
                mma16816(acc[2][nt], af[2], bf);
                mma16816(acc[3][nt], af[3], bf);
            }
        }

        if (c + 3 < KC)
            gemm_issue_h(A, Bp, sb, c + 3, tm0, np, K, KC, tid);
    }

    void* Cd; int ldc, coff;
    if (!fused)            { Cd = C0; ldc = N;    coff = 0;    }
    else if (tn0 < 2048)   { Cd = C0; ldc = 2048; coff = 0;    }
    else if (tn0 < 2560)   { Cd = C1; ldc = 512;  coff = 2048; }
    else                   { Cd = C2; ldc = 512;  coff = 2560; }

#pragma unroll
    for (int mt = 0; mt < 4; mt++) {
#pragma unroll
        for (int nt = 0; nt < 4; nt++) {
            int row = tm0 + wm * 64 + mt * 16 + g;
            int col = tn0 + wn * 32 + nt * 8 + t * 2 - coff;
            float4 a = acc[mt][nt];
            if (half_out) {
                uint32_t* H = (uint32_t*)Cd;
                H[((size_t)row * ldc + col) >> 1]       = packh2(a.x, a.y);
                H[((size_t)(row + 8) * ldc + col) >> 1] = packh2(a.z, a.w);
            } else {
                float* F = (float*)Cd;
                *(float2*)&F[(size_t)row * ldc + col] = make_float2(a.x, a.y);
                *(float2*)&F[(size_t)(row + 8) * ldc + col] = make_float2(a.z, a.w);
            }
        }
    }
}

// ---------------------------------------------------------------------------
// RoPE in place on fp16 q (folds 1/sqrt(HD)) and fp16 k.
// ---------------------------------------------------------------------------
__global__ void rope_h(__half* __restrict__ q, __half* __restrict__ k)
{
    const int NQ = BATCH * SQ * NH * 64;
    const int NK = BATCH * SQ * NKV * 64;
    int i = blockIdx.x * blockDim.x + threadIdx.x;
    if (i >= NQ + NK) return;

    __half* base;
    int d, s;
    float scale;
    if (i < NQ) {
        d = i & 63;
        int rest = i >> 6;
        s = (rest >> 4) & (SQ - 1);
        base = q + (size_t)rest * HD;
        scale = 0.08838834764831845f;
    } else {
        int j = i - NQ;
        d = j & 63;
        int rest = j >> 6;
        s = (rest >> 2) & (SQ - 1);
        base = k + (size_t)rest * HD;
        scale = 1.0f;
    }
    float inv_freq = powf(10000.0f, -(float)d * (1.0f / 64.0f));
    float ang = (float)s * inv_freq;
    float c = cosf(ang), sn = sinf(ang);
    float a = __half2float(base[d]), b = __half2float(base[d + 64]);
    base[d]      = __float2half((a * c - b * sn) * scale);
    base[d + 64] = __float2half((b * c + a * sn) * scale);
}

// ---------------------------------------------------------------------------
// V transpose: v fp16 [B,S,NKV,HD] -> vt fp16 [B,NKV,HD,SQ]
// ---------------------------------------------------------------------------
__global__ void vt_kernel(const __half* __restrict__ v, __half* __restrict__ vt)
{
    __shared__ float tile[32][33];
    const int s0 = blockIdx.x * 32, d0 = blockIdx.y * 32;
    const int bk = blockIdx.z;
    const int x = threadIdx.x, y = threadIdx.y;
#pragma unroll
    for (int i = 0; i < 32; i += 8)
        tile[y + i][x] = __half2float(
            v[((size_t)(bk / NKV * SQ + s0 + y + i) * NKV + (bk % NKV)) * HD + d0 + x]);
    __syncthreads();
#pragma unroll
    for (int i = 0; i < 32; i += 8)
        vt[((size_t)bk * HD + d0 + y + i) * SQ + s0 + x] = __float2half(tile[x][y + i]);
}

// ---------------------------------------------------------------------------
// FP16 flash attention v3: cp.async staging (no reg staging), 2 CTAs/SM.
// K double-buffered, V single-buffered. 3 syncthreads + cp waits per tile.
// Word offsets: Q 0 (128x68), K0 8704, K1 13056 (64x68 each),
// VT 17408 (128x36), PS 22016 (128x36), MB 26624, LB 26880. 108544 B.
// ---------------------------------------------------------------------------
#define AQS 0
#define AK0 8704
#define AK1 13056
#define AVT 17408
#define APS 22016
#define AMB 26624
#define ALB 26880
#define ATT_SMEM (27136 * 4)

__global__ __launch_bounds__(256, 2) void attn_h(
    const __half* __restrict__ qh, const __half* __restrict__ kh,
    const __half* __restrict__ vth, __half* __restrict__ outh)
{
    extern __shared__ float sm[];
    uint32_t* smw = (uint32_t*)sm;
    const uint32_t sb = smem_u32(sm);
    const int tid = threadIdx.x;
    const int lane = tid & 31, wid = tid >> 5;
    const int g = lane >> 2, t = lane & 3;
    const int wm = wid & 3, wn = wid >> 2;
    const int qt = gridDim.x - 1 - blockIdx.x;   // LPT
    const int h = blockIdx.y, b = blockIdx.z;
    const int kvh = h >> 2;
    const int q0 = qt * 128;

    const uint4* q16 = (const uint4*)qh;
    const int krow = tid >> 4, kc16 = tid & 15;      // K: 64 rows x 16 seg (4 iters)
    const int vrow = tid >> 3, vc16 = tid & 7;       // V: 128 rows x 8 seg (4 iters)
    const __half* ksrc = kh + ((size_t)(b * SQ) * NKV + kvh) * HD;
    const __half* vsrc = vth + (size_t)(b * NKV + kvh) * HD * SQ;

    // ---- prologue: Q tile (plain), K0+K1 via cp.async ----
#pragma unroll
    for (int i = 0; i < 8; i++) {
        int f = i * 256 + tid;
        int row = f >> 4, c = f & 15;
        uint4 v = q16[((size_t)(b * SQ + q0 + row) * NH + h) * 16 + c];
        *(uint4*)&smw[AQS + row * 68 + c * 4] = v;
    }
#pragma unroll
    for (int i = 0; i < 4; i++) {
        int row = i * 16 + krow;
        cp_async16(sb + (AK0 + row * 68 + kc16 * 4) * 4,
                   ksrc + (size_t)row * NKV * HD + kc16 * 8);
    }
    asm volatile("cp.async.commit_group;" ::: "memory");
#pragma unroll
    for (int i = 0; i < 4; i++) {
        int row = i * 16 + krow;
        cp_async16(sb + (AK1 + row * 68 + kc16 * 4) * 4,
                   ksrc + (size_t)(64 + row) * NKV * HD + kc16 * 8);
    }
    asm volatile("cp.async.commit_group;" ::: "memory");
    asm volatile("cp.async.wait_group 1;" ::: "memory");   // K0 done

    float4 oacc[2][8];
#pragma unroll
    for (int i = 0; i < 2; i++)
#pragma unroll
        for (int j = 0; j < 8; j++) oacc[i][j] = make_float4(0.f, 0.f, 0.f, 0.f);
    float m_s[2][2] = {{-1e30f, -1e30f}, {-1e30f, -1e30f}};
    float l_s[2][2] = {{0.f, 0.f}, {0.f, 0.f}};

    const int r0 = wm * 32 + g;
    const int ntiles = 2 * qt + 2;

    for (int kt = 0; kt < ntiles; kt++) {
        const int k0 = kt * 64;
        const int KB = (kt & 1) ? AK1 : AK0;
        const bool more = (kt + 2 < ntiles);

        __syncthreads();   // top: K(kt) visible (wait done pre-loop / prev iter); prev PV done

        // issue V(kt) — buffer free (PV of kt-1 done by top sync)
#pragma unroll
        for (int i = 0; i < 4; i++) {
            int row = i * 32 + vrow;
            cp_async16(sb + (AVT + row * 36 + vc16 * 4) * 4,
                       vsrc + (size_t)row * SQ + k0 + vc16 * 8);
        }
        asm volatile("cp.async.commit_group;" ::: "memory");

        // ---- S = Q @ K^T ----
        float4 sacc[2][4];
#pragma unroll
        for (int i = 0; i < 2; i++)
#pragma unroll
            for (int j = 0; j < 4; j++) sacc[i][j] = make_float4(0.f, 0.f, 0.f, 0.f);
#pragma unroll
        for (int ks = 0; ks < 8; ks++) {
            const int c0 = ks * 8 + t;
            uint32_t af[2][4];
#pragma unroll
            for (int mt = 0; mt < 2; mt++) {
                int rb = AQS + (r0 + mt * 16) * 68 + c0;
                af[mt][0] = smw[rb];
                af[mt][1] = smw[rb + 68 * 8];
                af[mt][2] = smw[rb + 4];
                af[mt][3] = smw[rb + 68 * 8 + 4];
            }
#pragma unroll
            for (int nt = 0; nt < 4; nt++) {
                int nb = KB + (wn * 32 + nt * 8 + g) * 68 + c0;
                uint2 bf = make_uint2(smw[nb], smw[nb + 4]);
                mma16816(sacc[0][nt], af[0], bf);
                mma16816(sacc[1][nt], af[1], bf);
            }
        }

        // ---- causal mask + row max ----
        if (kt >= 2 * qt) {
#pragma unroll
            for (int mt = 0; mt < 2; mt++)
#pragma unroll
                for (int nt = 0; nt < 4; nt++) {
                    int colb = k0 + wn * 32 + nt * 8 + 2 * t;
                    int rowb = q0 + wm * 32 + mt * 16 + g;
                    float* sc = (float*)&sacc[mt][nt];
                    if (colb     > rowb)     sc[0] = -1e30f;
                    if (colb + 1 > rowb)     sc[1] = -1e30f;
                    if (colb     > rowb + 8) sc[2] = -1e30f;
                    if (colb + 1 > rowb + 8) sc[3] = -1e30f;
                }
        }
        float rmax[2][2] = {{-1e30f, -1e30f}, {-1e30f, -1e30f}};
#pragma unroll
        for (int mt = 0; mt < 2; mt++)
#pragma unroll
            for (int nt = 0; nt < 4; nt++) {
                float4 s4 = sacc[mt][nt];
                rmax[mt][0] = fmaxf(rmax[mt][0], fmaxf(s4.x, s4.y));
                rmax[mt][1] = fmaxf(rmax[mt][1], fmaxf(s4.z, s4.w));
            }
#pragma unroll
        for (int mt = 0; mt < 2; mt++)
#pragma unroll
            for (int hf = 0; hf < 2; hf++) {
                float x = rmax[mt][hf];
                x = fmaxf(x, __shfl_xor_sync(0xffffffffu, x, 1));
                x = fmaxf(x, __shfl_xor_sync(0xffffffffu, x, 2));
                rmax[mt][hf] = x;
            }
        if (t == 0) {
#pragma unroll
            for (int mt = 0; mt < 2; mt++)
#pragma unroll
                for (int hf = 0; hf < 2; hf++)
                    sm[AMB + wn * 128 + wm * 32 + mt * 16 + hf * 8 + g] = rmax[mt][hf];
        }
        __syncthreads();   // sync2: MB visible; K(kt) consumed by all warps

        // issue K(kt+2) into KB (just freed)
        if (more) {
#pragma unroll
            for (int i = 0; i < 4; i++) {
                int row = i * 16 + krow;
                cp_async16(sb + (KB + row * 68 + kc16 * 4) * 4,
                           ksrc + (size_t)(k0 + 128 + row) * NKV * HD + kc16 * 8);
            }
        }
        asm volatile("cp.async.commit_group;" ::: "memory");  // (empty group ok)

        // ---- softmax ----
        float alpha[2][2];
#pragma unroll
        for (int mt = 0; mt < 2; mt++)
#pragma unroll
            for (int hf = 0; hf < 2; hf++) {
                int row = wm * 32 + mt * 16 + hf * 8 + g;
                float mn = fmaxf(m_s[mt][hf],
                                 fmaxf(sm[AMB + row], sm[AMB + 128 + row]));
                alpha[mt][hf] = __expf(m_s[mt][hf] - mn);
                m_s[mt][hf] = mn;
            }
        float rsum[2][2] = {{0.f, 0.f}, {0.f, 0.f}};
#pragma unroll
        for (int mt = 0; mt < 2; mt++)
#pragma unroll
            for (int nt = 0; nt < 4; nt++) {
                float4 s4 = sacc[mt][nt];
                float p0 = __expf(s4.x - m_s[mt][0]);
                float p1 = __expf(s4.y - m_s[mt][0]);
                float p2 = __expf(s4.z - m_s[mt][1]);
                float p3 = __expf(s4.w - m_s[mt][1]);
                rsum[mt][0] += p0 + p1;
                rsum[mt][1] += p2 + p3;
                int cw = wn * 16 + nt * 4 + t;
                int rl = wm * 32 + mt * 16 + g;
                smw[APS + rl * 36 + cw]       = packh2(p0, p1);
                smw[APS + (rl + 8) * 36 + cw] = packh2(p2, p3);
            }
#pragma unroll
        for (int mt = 0; mt < 2; mt++)
#pragma unroll
            for (int hf = 0; hf < 2; hf++) {
                float x = rsum[mt][hf];
                x += __shfl_xor_sync(0xffffffffu, x, 1);
                x += __shfl_xor_sync(0xffffffffu, x, 2);
                rsum[mt][hf] = x;
            }
        if (t == 0) {
#pragma unroll
            for (int mt = 0; mt < 2; mt++)
#pragma unroll
                for (int hf = 0; hf < 2; hf++)
                    sm[ALB + wn * 128 + wm * 32 + mt * 16 + hf * 8 + g] = rsum[mt][hf];
        }
#pragma unroll
        for (int mt = 0; mt < 2; mt++)
#pragma unroll
            for (int nt = 0; nt < 8; nt++) {
                oacc[mt][nt].x *= alpha[mt][0];
                oacc[mt][nt].y *= alpha[mt][0];
                oacc[mt][nt].z *= alpha[mt][1];
                oacc[mt][nt].w *= alpha[mt][1];
            }

        // wait V(kt) (newest pending = K(kt+2) group), then visibility sync
        if (more) asm volatile("cp.async.wait_group 1;" ::: "memory");
        else      asm volatile("cp.async.wait_group 0;" ::: "memory");
        __syncthreads();   // sync3: P, LB, V(kt) visible

        // ---- l update + O += P @ V ----
#pragma unroll
        for (int mt = 0; mt < 2; mt++)
#pragma unroll
            for (int hf = 0; hf < 2; hf++) {
                int row = wm * 32 + mt * 16 + hf * 8 + g;
                l_s[mt][hf] = l_s[mt][hf] * alpha[mt][hf]
                            + sm[ALB + row] + sm[ALB + 128 + row];
            }
#pragma unroll
        for (int ks = 0; ks < 4; ks++) {
            const int c0 = ks * 8 + t;
            uint32_t af[2][4];
#pragma unroll
            for (int mt = 0; mt < 2; mt++) {
                int rb = APS + (r0 + mt * 16) * 36 + c0;
                af[mt][0] = smw[rb];
                af[mt][1] = smw[rb + 36 * 8];
                af[mt][2] = smw[rb + 4];
                af[mt][3] = smw[rb + 36 * 8 + 4];
            }
#pragma unroll
            for (int nt = 0; nt < 8; nt++) {
                int nb = AVT + (wn * 64 + nt * 8 + g) * 36 + c0;
                uint2 bf = make_uint2(smw[nb], smw[nb + 4]);
                mma16816(oacc[0][nt], af[0], bf);
                mma16816(oacc[1][nt], af[1], bf);
            }
        }
    }

    // ---- epilogue: fp16 out ----
    uint32_t* outw = (uint32_t*)outh;
#pragma unroll
    for (int mt = 0; mt < 2; mt++) {
        float i0 = 1.f / l_s[mt][0], i1 = 1.f / l_s[mt][1];
#pragma unroll
        for (int nt = 0; nt < 8; nt++) {
            int row = q0 + wm * 32 + mt * 16 + g;
            int cw = h * 64 + wn * 32 + nt * 4 + t;
            float4 o = oacc[mt][nt];
            outw[(size_t)(b * SQ + row) * 1024 + cw]     = packh2(o.x * i0, o.y * i0);
            outw[(size_t)(b * SQ + row + 8) * 1024 + cw] = packh2(o.z * i1, o.w * i1);
        }
    }
}

// ---------------------------------------------------------------------------
extern "C" void kernel_launch(void* const* d_in, const int* in_sizes, int n_in,
                              void* d_out, int out_size)
{
    const float* x  = (const float*)d_in[0];
    const float* Wq = (const float*)d_in[1];
    const float* Wk = (const float*)d_in[2];
    const float* Wv = (const float*)d_in[3];
    const float* Wo = (const float*)d_in[4];

    __half *xh, *qh, *kh, *vh, *vth, *ah, *wh;
    cudaGetSymbolAddress((void**)&xh, g_xh);
    cudaGetSymbolAddress((void**)&qh, g_qh);
    cudaGetSymbolAddress((void**)&kh, g_kh);
    cudaGetSymbolAddress((void**)&vh, g_vh);
    cudaGetSymbolAddress((void**)&vth, g_vth);
    cudaGetSymbolAddress((void**)&ah, g_ah);
    cudaGetSymbolAddress((void**)&wh, g_wh);

    const int M = BATCH * SQ;   // 4096

    cudaFuncSetAttribute(gemm_h, cudaFuncAttributeMaxDynamicSharedMemorySize,
                         GEMM_SMEM);
    cudaFuncSetAttribute(attn_h, cudaFuncAttributeMaxDynamicSharedMemorySize,
                         ATT_SMEM);

    // x -> fp16; pack Q|K|V weights
    cvt_x<<<(M * EB / 4 + 255) / 256, 256>>>(x, xh, M * EB / 4);
    pack_bh<<<(EB * EB / 2 + 255) / 256, 256>>>(Wq, wh, EB, EB);
    pack_bh<<<(EB * KVDIM / 2 + 255) / 256, 256>>>(Wk, wh + 16 * 262144, EB, KVDIM);
    pack_bh<<<(EB * KVDIM / 2 + 255) / 256, 256>>>(Wv, wh + 20 * 262144, EB, KVDIM);

    // Fused QKV projection -> fp16 q/k/v
    gemm_h<<<dim3(3072 / 128, M / 256), 512, GEMM_SMEM>>>(
        xh, wh, qh, kh, vh, M, 3072, EB, 1, 1);

    // RoPE in place; V transpose
    int npairs = BATCH * SQ * (NH + NKV) * 64;
    rope_h<<<(npairs + 255) / 256, 256>>>(qh, kh);
    vt_kernel<<<dim3(SQ / 32, HD / 32, BATCH * NKV), dim3(32, 8)>>>(vh, vth);

    // Flash attention (2 CTAs/SM)
    attn_h<<<dim3(SQ / 128, NH, BATCH), 256, ATT_SMEM>>>(qh, kh, vth, ah);

    // Output projection (fp32 out)
    pack_bh<<<(EB * EB / 2 + 255) / 256, 256>>>(Wo, wh, EB, EB);
    gemm_h<<<dim3(EB / 128, M / 256), 512, GEMM_SMEM>>>(
        ah, wh, d_out, nullptr, nullptr, M, EB, EB, 0, 0);
}

// round 10
// speedup vs baseline: 1.6394x; 1.0181x over previous
#include <cuda_runtime.h>
#include <cuda_fp16.h>
#include <cstdint>

#define SQ    2048
#define EB    2048
#define BATCH 2
#define NH    16
#define NKV   4
#define HD    128
#define KVDIM (NKV*HD)

// Scratch (device globals — allocation inside kernel_launch is forbidden)
__device__ __half g_xh[BATCH * SQ * EB];          // x fp16
__device__ __half g_qh[BATCH * SQ * NH * HD];     // q fp16 (gemm out, roped in place)
__device__ __half g_kh[BATCH * SQ * NKV * HD];    // k fp16 (gemm out, roped in place)
__device__ __half g_vh[BATCH * SQ * NKV * HD];    // v fp16 (gemm out)
__device__ __half g_vth[BATCH * NKV * HD * SQ];   // v transposed fp16
__device__ __half g_ah[BATCH * SQ * EB];          // attn out fp16
__device__ __half g_wh[EB * 3072];                // packed weights fp16

// ---------------------------------------------------------------------------
__device__ __forceinline__ uint32_t smem_u32(const void* p) {
    uint32_t a;
    asm("{ .reg .u64 t; cvta.to.shared.u64 t, %1; cvt.u32.u64 %0, t; }"
        : "=r"(a) : "l"(p));
    return a;
}

__device__ __forceinline__ uint32_t packh2(float a, float b) {
    __half2 h = __floats2half2_rn(a, b);
    return *(uint32_t*)&h;
}

__device__ __forceinline__ void cp_async16(uint32_t smem_addr, const void* gptr) {
    asm volatile("cp.async.cg.shared.global [%0], [%1], 16;"
                 :: "r"(smem_addr), "l"(gptr));
}

__device__ __forceinline__ void mma16816(float4& d, const uint32_t* a, uint2 b) {
    asm volatile(
        "mma.sync.aligned.m16n8k16.row.col.f32.f16.f16.f32 "
        "{%0,%1,%2,%3}, {%4,%5,%6,%7}, {%8,%9}, {%0,%1,%2,%3};"
        : "+f"(d.x), "+f"(d.y), "+f"(d.z), "+f"(d.w)
        : "r"(a[0]), "r"(a[1]), "r"(a[2]), "r"(a[3]), "r"(b.x), "r"(b.y));
}

// ---------------------------------------------------------------------------
__global__ void cvt_x(const float* __restrict__ x, __half* __restrict__ xh, int n4)
{
    int i = blockIdx.x * blockDim.x + threadIdx.x;
    if (i >= n4) return;
    float4 v = ((const float4*)x)[i];
    ((uint2*)xh)[i] = make_uint2(packh2(v.x, v.y), packh2(v.z, v.w));
}

// ---------------------------------------------------------------------------
// Pack W[k][n] (KxN fp32 row-major) into fp16 m16n8k16 B-fragment order.
// ---------------------------------------------------------------------------
__global__ void pack_bh(const float* __restrict__ W, __half* __restrict__ Bp,
                        int K, int N)
{
    int gid = blockIdx.x * blockDim.x + threadIdx.x;
    int total = (K * N) >> 1;
    if (gid >= total) return;
    const int KC = K / 32;
    int j    = gid & 1;
    int lane = (gid >> 1) & 31;
    int kh   = (gid >> 6) & 1;
    int nt   = (gid >> 7) & 15;
    int kc   = (gid >> 11) % KC;
    int np   = (gid >> 11) / KC;
    int n = np * 128 + nt * 8 + (lane >> 2);
    int k = kc * 32 + kh * 16 + (lane & 3) * 2 + j * 8;
    ((uint32_t*)Bp)[gid] = packh2(W[(size_t)k * N + n], W[(size_t)(k + 1) * N + n]);
}

// ---------------------------------------------------------------------------
// FP16 GEMM: CTA 256x128, 512 thr, warp tile 64x32, 4-stage cp.async.
// ---------------------------------------------------------------------------
#define GEMM_SMEM 114688
#define GSTW 7168

__device__ __forceinline__ void gemm_issue_h(
    const __half* __restrict__ A, const __half* __restrict__ Bp,
    uint32_t sb, int c, int tm0, int np, int K, int KC, int tid)
{
    const uint32_t base = sb + (c & 3) * 28672;
#pragma unroll
    for (int i = 0; i < 2; i++) {
        int f = i * 512 + tid;
        int row = f >> 2, gc = f & 3;
        cp_async16(base + row * 80 + gc * 16,
                   A + (size_t)(tm0 + row) * K + c * 32 + gc * 8);
    }
    cp_async16(base + 20480 + tid * 16,
               Bp + ((size_t)np * KC + c) * 4096 + tid * 8);
    asm volatile("cp.async.commit_group;" ::: "memory");
}

__global__ __launch_bounds__(512, 1) void gemm_h(
    const __half* __restrict__ A, const __half* __restrict__ Bp,
    void* __restrict__ C0, void* __restrict__ C1, void* __restrict__ C2,
    int M, int N, int K, int fused, int half_out)
{
    extern __shared__ float sm[];
    uint32_t* smw = (uint32_t*)sm;
    const int tid = threadIdx.x;
    const int lane = tid & 31, wid = tid >> 5;
    const int g = lane >> 2, t = lane & 3;
    const int wm = wid & 3, wn = wid >> 2;
    const int tm0 = blockIdx.y * 256, tn0 = blockIdx.x * 128;
    const int np = blockIdx.x;
    const int KC = K / 32;
    const uint32_t sb = smem_u32(sm);

    float4 acc[4][4];
#pragma unroll
    for (int i = 0; i < 4; i++)
#pragma unroll
        for (int j = 0; j < 4; j++) acc[i][j] = make_float4(0.f, 0.f, 0.f, 0.f);

    gemm_issue_h(A, Bp, sb, 0, tm0, np, K, KC, tid);
    gemm_issue_h(A, Bp, sb, 1, tm0, np, K, KC, tid);
    gemm_issue_h(A, Bp, sb, 2, tm0, np, K, KC, tid);

    const int r0 = wm * 64 + g;

    for (int c = 0; c < KC; c++) {
        const int rem = KC - 1 - c;
        if (rem >= 2)      asm volatile("cp.async.wait_group 2;" ::: "memory");
        else if (rem == 1) asm volatile("cp.async.wait_group 1;" ::: "memory");
        else               asm volatile("cp.async.wait_group 0;" ::: "memory");
        __syncthreads();

        const uint32_t* As = smw + (c & 3) * GSTW;
        const uint32_t* Bs = As + 5120;

#pragma unroll
        for (int kh = 0; kh < 2; kh++) {
            uint32_t af[4][4];
#pragma unroll
            for (int mt = 0; mt < 4; mt++) {
                const int rb = (r0 + mt * 16) * 20 + kh * 8 + t;
                af[mt][0] = As[rb];
                af[mt][1] = As[rb + 8 * 20];
                af[mt][2] = As[rb + 4];
                af[mt][3] = As[rb + 8 * 20 + 4];
            }
#pragma unroll
            for (int nt = 0; nt < 4; nt++) {
                uint2 bf = *(const uint2*)&Bs[(((wn * 4 + nt) * 2 + kh) * 32 + lane) * 2];
                mma16816(acc[0][nt], af[0], bf);
                mma16816(acc[1][nt], af[1], bf);
                mma16816(acc[2][nt], af[2], bf);
                mma16816(acc[3][nt], af[3], bf);
            }
        }

        if (c + 3 < KC)
            gemm_issue_h(A, Bp, sb, c + 3, tm0, np, K, KC, tid);
    }

    void* Cd; int ldc, coff;
    if (!fused)            { Cd = C0; ldc = N;    coff = 0;    }
    else if (tn0 < 2048)   { Cd = C0; ldc = 2048; coff = 0;    }
    else if (tn0 < 2560)   { Cd = C1; ldc = 512;  coff = 2048; }
    else                   { Cd = C2; ldc = 512;  coff = 2560; }

#pragma unroll
    for (int mt = 0; mt < 4; mt++) {
#pragma unroll
        for (int nt = 0; nt < 4; nt++) {
            int row = tm0 + wm * 64 + mt * 16 + g;
            int col = tn0 + wn * 32 + nt * 8 + t * 2 - coff;
            float4 a = acc[mt][nt];
            if (half_out) {
                uint32_t* H = (uint32_t*)Cd;
                H[((size_t)row * ldc + col) >> 1]       = packh2(a.x, a.y);
                H[((size_t)(row + 8) * ldc + col) >> 1] = packh2(a.z, a.w);
            } else {
                float* F = (float*)Cd;
                *(float2*)&F[(size_t)row * ldc + col] = make_float2(a.x, a.y);
                *(float2*)&F[(size_t)(row + 8) * ldc + col] = make_float2(a.z, a.w);
            }
        }
    }
}

// ---------------------------------------------------------------------------
// RoPE in place on fp16 q (folds 1/sqrt(HD)) and fp16 k.
// ---------------------------------------------------------------------------
__global__ void rope_h(__half* __restrict__ q, __half* __restrict__ k)
{
    const int NQ = BATCH * SQ * NH * 64;
    const int NK = BATCH * SQ * NKV * 64;
    int i = blockIdx.x * blockDim.x + threadIdx.x;
    if (i >= NQ + NK) return;

    __half* base;
    int d, s;
    float scale;
    if (i < NQ) {
        d = i & 63;
        int rest = i >> 6;
        s = (rest >> 4) & (SQ - 1);
        base = q + (size_t)rest * HD;
        scale = 0.08838834764831845f;
    } else {
        int j = i - NQ;
        d = j & 63;
        int rest = j >> 6;
        s = (rest >> 2) & (SQ - 1);
        base = k + (size_t)rest * HD;
        scale = 1.0f;
    }
    float inv_freq = powf(10000.0f, -(float)d * (1.0f / 64.0f));
    float ang = (float)s * inv_freq;
    float c = cosf(ang), sn = sinf(ang);
    float a = __half2float(base[d]), b = __half2float(base[d + 64]);
    base[d]      = __float2half((a * c - b * sn) * scale);
    base[d + 64] = __float2half((b * c + a * sn) * scale);
}

// ---------------------------------------------------------------------------
// V transpose: v fp16 [B,S,NKV,HD] -> vt fp16 [B,NKV,HD,SQ]
// ---------------------------------------------------------------------------
__global__ void vt_kernel(const __half* __restrict__ v, __half* __restrict__ vt)
{
    __shared__ float tile[32][33];
    const int s0 = blockIdx.x * 32, d0 = blockIdx.y * 32;
    const int bk = blockIdx.z;
    const int x = threadIdx.x, y = threadIdx.y;
#pragma unroll
    for (int i = 0; i < 32; i += 8)
        tile[y + i][x] = __half2float(
            v[((size_t)(bk / NKV * SQ + s0 + y + i) * NKV + (bk % NKV)) * HD + d0 + x]);
    __syncthreads();
#pragma unroll
    for (int i = 0; i < 32; i += 8)
        vt[((size_t)bk * HD + d0 + y + i) * SQ + s0 + x] = __float2half(tile[x][y + i]);
}

// ---------------------------------------------------------------------------
// FP16 flash attention v4 (FA2-style):
// 8 warps x 16 q-rows; each warp owns ALL 64 keys & all 128 d.
// P stays in registers (S C-frag -> PV A-frag via packh2). Warp-local stats.
// K and V double-buffered cp.async; ONE __syncthreads per key tile.
// Word offsets: Q 0 (128x68), K0 8704, K1 13056 (64x68), V0 17408, V1 22016
// (128x36 each). Total 26624 words = 106496 B -> 2 CTAs/SM.
// ---------------------------------------------------------------------------
#define AQS 0
#define AK0 8704
#define AK1 13056
#define AV0 17408
#define AV1 22016
#define ATT_SMEM (26624 * 4)

__global__ __launch_bounds__(256, 2) void attn_h(
    const __half* __restrict__ qh, const __half* __restrict__ kh,
    const __half* __restrict__ vth, __half* __restrict__ outh)
{
    extern __shared__ float sm[];
    uint32_t* smw = (uint32_t*)sm;
    const uint32_t sb = smem_u32(sm);
    const int tid = threadIdx.x;
    const int lane = tid & 31, wid = tid >> 5;
    const int g = lane >> 2, t = lane & 3;
    const int qt = gridDim.x - 1 - blockIdx.x;   // LPT: heavy tiles first
    const int h = blockIdx.y, b = blockIdx.z;
    const int kvh = h >> 2;
    const int q0 = qt * 128;

    const uint4* q16 = (const uint4*)qh;
    const int krow = tid >> 4, kc16 = tid & 15;      // K: 64 rows x 16 cp16
    const int vrow = tid >> 3, vc16 = tid & 7;       // V: 128 rows x 8 cp16
    const __half* ksrc = kh + ((size_t)(b * SQ) * NKV + kvh) * HD;
    const __half* vsrc = vth + (size_t)(b * NKV + kvh) * HD * SQ;

    // ---- prologue: Q tile (plain LDG/STS), G0 = {K(0), V(0)} via cp.async ----
#pragma unroll
    for (int i = 0; i < 8; i++) {
        int f = i * 256 + tid;
        int row = f >> 4, c = f & 15;
        uint4 v = q16[((size_t)(b * SQ + q0 + row) * NH + h) * 16 + c];
        *(uint4*)&smw[AQS + row * 68 + c * 4] = v;
    }
#pragma unroll
    for (int i = 0; i < 4; i++) {
        int row = i * 16 + krow;
        cp_async16(sb + (AK0 + row * 68 + kc16 * 4) * 4,
                   ksrc + (size_t)row * NKV * HD + kc16 * 8);
    }
#pragma unroll
    for (int i = 0; i < 4; i++) {
        int row = i * 32 + vrow;
        cp_async16(sb + (AV0 + row * 36 + vc16 * 4) * 4,
                   vsrc + (size_t)row * SQ + vc16 * 8);
    }
    asm volatile("cp.async.commit_group;" ::: "memory");

    float4 oacc[16];
#pragma unroll
    for (int j = 0; j < 16; j++) oacc[j] = make_float4(0.f, 0.f, 0.f, 0.f);
    float m_s[2] = {-1e30f, -1e30f};
    float l_s[2] = {0.f, 0.f};

    const int r0 = wid * 16 + g;     // warp-local q row (and +8)
    const int ntiles = 2 * qt + 2;

    for (int kt = 0; kt < ntiles; kt++) {
        const int k0 = kt * 64;
        const uint32_t KB = (kt & 1) ? AK1 : AK0;
        const uint32_t VB = (kt & 1) ? AV1 : AV0;

        // G(kt) arrived; one barrier: visibility + buffer-reuse safety
        asm volatile("cp.async.wait_group 0;" ::: "memory");
        __syncthreads();

        // issue G(kt+1) into the other buffers (read last at kt-1, now safe)
        if (kt + 1 < ntiles) {
            const int kk = k0 + 64;
            const uint32_t KBn = (kt & 1) ? AK0 : AK1;
            const uint32_t VBn = (kt & 1) ? AV0 : AV1;
#pragma unroll
            for (int i = 0; i < 4; i++) {
                int row = i * 16 + krow;
                cp_async16(sb + (KBn + row * 68 + kc16 * 4) * 4,
                           ksrc + (size_t)(kk + row) * NKV * HD + kc16 * 8);
            }
#pragma unroll
            for (int i = 0; i < 4; i++) {
                int row = i * 32 + vrow;
                cp_async16(sb + (VBn + row * 36 + vc16 * 4) * 4,
                           vsrc + (size_t)row * SQ + kk + vc16 * 8);
            }
            asm volatile("cp.async.commit_group;" ::: "memory");
        }

        // ---- S = Q @ K^T : 16 rows x 64 keys per warp ----
        float4 sacc[8];
#pragma unroll
        for (int j = 0; j < 8; j++) sacc[j] = make_float4(0.f, 0.f, 0.f, 0.f);
#pragma unroll
        for (int ks = 0; ks < 8; ks++) {
            const int c0 = ks * 8 + t;
            uint32_t af[4];
            {
                int rb = AQS + r0 * 68 + c0;
                af[0] = smw[rb];
                af[1] = smw[rb + 68 * 8];
                af[2] = smw[rb + 4];
                af[3] = smw[rb + 68 * 8 + 4];
            }
#pragma unroll
            for (int nt = 0; nt < 8; nt++) {
                int nb = KB + (nt * 8 + g) * 68 + c0;
                uint2 bf = make_uint2(smw[nb], smw[nb + 4]);
                mma16816(sacc[nt], af, bf);
            }
        }

        // ---- causal mask (diagonal tiles only) ----
        if (kt >= 2 * qt) {
            const int rowb = q0 + r0;
#pragma unroll
            for (int nt = 0; nt < 8; nt++) {
                int colb = k0 + nt * 8 + 2 * t;
                float* sc = (float*)&sacc[nt];
                if (colb     > rowb)     sc[0] = -1e30f;
                if (colb + 1 > rowb)     sc[1] = -1e30f;
                if (colb     > rowb + 8) sc[2] = -1e30f;
                if (colb + 1 > rowb + 8) sc[3] = -1e30f;
            }
        }

        // ---- warp-local row max (quad shuffles only) ----
        float rmax[2] = {-1e30f, -1e30f};
#pragma unroll
        for (int nt = 0; nt < 8; nt++) {
            rmax[0] = fmaxf(rmax[0], fmaxf(sacc[nt].x, sacc[nt].y));
            rmax[1] = fmaxf(rmax[1], fmaxf(sacc[nt].z, sacc[nt].w));
        }
#pragma unroll
        for (int hf = 0; hf < 2; hf++) {
            float x = rmax[hf];
            x = fmaxf(x, __shfl_xor_sync(0xffffffffu, x, 1));
            x = fmaxf(x, __shfl_xor_sync(0xffffffffu, x, 2));
            rmax[hf] = x;
        }
        float alpha[2];
#pragma unroll
        for (int hf = 0; hf < 2; hf++) {
            float mn = fmaxf(m_s[hf], rmax[hf]);
            alpha[hf] = __expf(m_s[hf] - mn);
            m_s[hf] = mn;
        }

        // ---- exp + row sum + pack P directly into PV A-fragments ----
        uint32_t pa[4][4];
        float rsum[2] = {0.f, 0.f};
#pragma unroll
        for (int ks = 0; ks < 4; ks++) {
            float4 s0 = sacc[2 * ks], s1 = sacc[2 * ks + 1];
            float p00 = __expf(s0.x - m_s[0]), p01 = __expf(s0.y - m_s[0]);
            float p02 = __expf(s0.z - m_s[1]), p03 = __expf(s0.w - m_s[1]);
            float p10 = __expf(s1.x - m_s[0]), p11 = __expf(s1.y - m_s[0]);
            float p12 = __expf(s1.z - m_s[1]), p13 = __expf(s1.w - m_s[1]);
            rsum[0] += p00 + p01 + p10 + p11;
            rsum[1] += p02 + p03 + p12 + p13;
            pa[ks][0] = packh2(p00, p01);   // row g,   keys 16ks+2t
            pa[ks][1] = packh2(p02, p03);   // row g+8, keys 16ks+2t
            pa[ks][2] = packh2(p10, p11);   // row g,   keys 16ks+8+2t
            pa[ks][3] = packh2(p12, p13);   // row g+8, keys 16ks+8+2t
        }
#pragma unroll
        for (int hf = 0; hf < 2; hf++) {
            float x = rsum[hf];
            x += __shfl_xor_sync(0xffffffffu, x, 1);
            x += __shfl_xor_sync(0xffffffffu, x, 2);
            l_s[hf] = l_s[hf] * alpha[hf] + x;
        }
#pragma unroll
        for (int nt = 0; nt < 16; nt++) {
            oacc[nt].x *= alpha[0];
            oacc[nt].y *= alpha[0];
            oacc[nt].z *= alpha[1];
            oacc[nt].w *= alpha[1];
        }

        // ---- O += P @ V (P in registers) ----
#pragma unroll
        for (int ks = 0; ks < 4; ks++) {
            const int c0 = ks * 8 + t;
#pragma unroll
            for (int nt = 0; nt < 16; nt++) {
                int nb = VB + (nt * 8 + g) * 36 + c0;
                uint2 bf = make_uint2(smw[nb], smw[nb + 4]);
                mma16816(oacc[nt], pa[ks], bf);
            }
        }
    }

    // ---- epilogue: fp16 out ----
    uint32_t* outw = (uint32_t*)outh;
    const float i0 = 1.f / l_s[0], i1 = 1.f / l_s[1];
    const int row = q0 + r0;
#pragma unroll
    for (int nt = 0; nt < 16; nt++) {
        int cw = h * 64 + nt * 4 + t;
        float4 o = oacc[nt];
        outw[(size_t)(b * SQ + row) * 1024 + cw]     = packh2(o.x * i0, o.y * i0);
        outw[(size_t)(b * SQ + row + 8) * 1024 + cw] = packh2(o.z * i1, o.w * i1);
    }
}

// ---------------------------------------------------------------------------
extern "C" void kernel_launch(void* const* d_in, const int* in_sizes, int n_in,
                              void* d_out, int out_size)
{
    const float* x  = (const float*)d_in[0];
    const float* Wq = (const float*)d_in[1];
    const float* Wk = (const float*)d_in[2];
    const float* Wv = (const float*)d_in[3];
    const float* Wo = (const float*)d_in[4];

    __half *xh, *qh, *kh, *vh, *vth, *ah, *wh;
    cudaGetSymbolAddress((void**)&xh, g_xh);
    cudaGetSymbolAddress((void**)&qh, g_qh);
    cudaGetSymbolAddress((void**)&kh, g_kh);
    cudaGetSymbolAddress((void**)&vh, g_vh);
    cudaGetSymbolAddress((void**)&vth, g_vth);
    cudaGetSymbolAddress((void**)&ah, g_ah);
    cudaGetSymbolAddress((void**)&wh, g_wh);

    const int M = BATCH * SQ;   // 4096

    cudaFuncSetAttribute(gemm_h, cudaFuncAttributeMaxDynamicSharedMemorySize,
                         GEMM_SMEM);
    cudaFuncSetAttribute(attn_h, cudaFuncAttributeMaxDynamicSharedMemorySize,
                         ATT_SMEM);

    // x -> fp16; pack Q|K|V weights
    cvt_x<<<(M * EB / 4 + 255) / 256, 256>>>(x, xh, M * EB / 4);
    pack_bh<<<(EB * EB / 2 + 255) / 256, 256>>>(Wq, wh, EB, EB);
    pack_bh<<<(EB * KVDIM / 2 + 255) / 256, 256>>>(Wk, wh + 16 * 262144, EB, KVDIM);
    pack_bh<<<(EB * KVDIM / 2 + 255) / 256, 256>>>(Wv, wh + 20 * 262144, EB, KVDIM);

    // Fused QKV projection -> fp16 q/k/v
    gemm_h<<<dim3(3072 / 128, M / 256), 512, GEMM_SMEM>>>(
        xh, wh, qh, kh, vh, M, 3072, EB, 1, 1);

    // RoPE in place; V transpose
    int npairs = BATCH * SQ * (NH + NKV) * 64;
    rope_h<<<(npairs + 255) / 256, 256>>>(qh, kh);
    vt_kernel<<<dim3(SQ / 32, HD / 32, BATCH * NKV), dim3(32, 8)>>>(vh, vth);

    // Flash attention v4 (register-resident P, 1 sync/tile, 2 CTAs/SM)
    attn_h<<<dim3(SQ / 128, NH, BATCH), 256, ATT_SMEM>>>(qh, kh, vth, ah);

    // Output projection (fp32 out)
    pack_bh<<<(EB * EB / 2 + 255) / 256, 256>>>(Wo, wh, EB, EB);
    gemm_h<<<dim3(EB / 128, M / 256), 512, GEMM_SMEM>>>(
        ah, wh, d_out, nullptr, nullptr, M, EB, EB, 0, 0);
}

// round 11
// speedup vs baseline: 1.7937x; 1.0941x over previous
#include <cuda_runtime.h>
#include <cuda_fp16.h>
#include <cstdint>

#define SQ    2048
#define EB    2048
#define BATCH 2
#define NH    16
#define NKV   4
#define HD    128
#define KVDIM (NKV*HD)

// Scratch (device globals — allocation inside kernel_launch is forbidden)
__device__ __half g_xh[BATCH * SQ * EB];          // x fp16
__device__ __half g_qh[BATCH * SQ * NH * HD];     // q fp16 (gemm out, roped in place)
__device__ __half g_kh[BATCH * SQ * NKV * HD];    // k fp16 (gemm out, roped in place)
__device__ __half g_vh[BATCH * SQ * NKV * HD];    // v fp16 (gemm out)
__device__ __half g_vth[BATCH * NKV * HD * SQ];   // v transposed fp16
__device__ __half g_ah[BATCH * SQ * EB];          // attn out fp16
__device__ __half g_wh[EB * 3072];                // packed QKV weights fp16
__device__ __half g_wo[EB * EB];                  // packed O weight fp16

// ---------------------------------------------------------------------------
__device__ __forceinline__ uint32_t smem_u32(const void* p) {
    uint32_t a;
    asm("{ .reg .u64 t; cvta.to.shared.u64 t, %1; cvt.u32.u64 %0, t; }"
        : "=r"(a) : "l"(p));
    return a;
}

__device__ __forceinline__ uint32_t packh2(float a, float b) {
    __half2 h = __floats2half2_rn(a, b);
    return *(uint32_t*)&h;
}

__device__ __forceinline__ void cp_async16(uint32_t smem_addr, const void* gptr) {
    asm volatile("cp.async.cg.shared.global [%0], [%1], 16;"
                 :: "r"(smem_addr), "l"(gptr));
}

__device__ __forceinline__ void mma16816(float4& d, const uint32_t* a, uint2 b) {
    asm volatile(
        "mma.sync.aligned.m16n8k16.row.col.f32.f16.f16.f32 "
        "{%0,%1,%2,%3}, {%4,%5,%6,%7}, {%8,%9}, {%0,%1,%2,%3};"
        : "+f"(d.x), "+f"(d.y), "+f"(d.z), "+f"(d.w)
        : "r"(a[0]), "r"(a[1]), "r"(a[2]), "r"(a[3]), "r"(b.x), "r"(b.y));
}

// ---------------------------------------------------------------------------
__global__ void cvt_x(const float* __restrict__ x, __half* __restrict__ xh, int n4)
{
    int i = blockIdx.x * blockDim.x + threadIdx.x;
    if (i >= n4) return;
    float4 v = ((const float4*)x)[i];
    ((uint2*)xh)[i] = make_uint2(packh2(v.x, v.y), packh2(v.z, v.w));
}

// ---------------------------------------------------------------------------
// Pack all four weights into fp16 m16n8k16 B-fragment order, one launch.
// Segments (in uint32 words): Wq 2097152 -> wh+0 (N=2048)
//   Wk 524288 -> wh+16*262144 (N=512), Wv 524288 -> wh+20*262144,
//   Wo 2097152 -> wo (N=2048). K=2048 for all.
// ---------------------------------------------------------------------------
__device__ __forceinline__ void pack_one(const float* W, __half* Bp,
                                         int gid, int N)
{
    const int KC = 64;   // K=2048
    int j    = gid & 1;
    int lane = (gid >> 1) & 31;
    int kh   = (gid >> 6) & 1;
    int nt   = (gid >> 7) & 15;
    int kc   = (gid >> 11) % KC;
    int np   = (gid >> 11) / KC;
    int n = np * 128 + nt * 8 + (lane >> 2);
    int k = kc * 32 + kh * 16 + (lane & 3) * 2 + j * 8;
    ((uint32_t*)Bp)[gid] = packh2(W[(size_t)k * N + n], W[(size_t)(k + 1) * N + n]);
}

__global__ void pack_all(const float* __restrict__ Wq, const float* __restrict__ Wk,
                         const float* __restrict__ Wv, const float* __restrict__ Wo,
                         __half* __restrict__ wh, __half* __restrict__ wo)
{
    int gid = blockIdx.x * blockDim.x + threadIdx.x;
    if (gid < 2097152)        pack_one(Wq, wh, gid, 2048);
    else if (gid < 2621440)   pack_one(Wk, wh + 16 * 262144, gid - 2097152, 512);
    else if (gid < 3145728)   pack_one(Wv, wh + 20 * 262144, gid - 2621440, 512);
    else if (gid < 5242880)   pack_one(Wo, wo, gid - 3145728, 2048);
}

// ---------------------------------------------------------------------------
// FP16 GEMM v2: CTA 256x128, 512 thr, warp tile 64x32.
// K-chunk 64 (half the barriers), 4-stage cp.async.
// Stage: A 256x(64h pad->72h)=36864B + B 8192h=16384B = 53248 B; x4 = 208 KB.
// ---------------------------------------------------------------------------
#define GEMM_SMEM 212992
#define GSTW 13312          // stage stride in words (53248/4)

__device__ __forceinline__ void gemm_issue_h(
    const __half* __restrict__ A, const __half* __restrict__ Bp,
    uint32_t sb, int c, int tm0, int np, int K, int KC32, int tid)
{
    const uint32_t base = sb + (c & 3) * 53248;
    // A: 256 rows x 8 cp16 (64 halves), row stride 144 B (36 words)
#pragma unroll
    for (int i = 0; i < 4; i++) {
        int f = i * 512 + tid;
        int row = f >> 3, seg = f & 7;
        cp_async16(base + row * 144 + seg * 16,
                   A + (size_t)(tm0 + row) * K + c * 64 + seg * 8);
    }
    // B: two packed 32-K blocks (2c, 2c+1) = 1024 cp16
#pragma unroll
    for (int i = 0; i < 2; i++) {
        int f = i * 512 + tid;
        cp_async16(base + 36864 + f * 16,
                   Bp + ((size_t)np * KC32 + 2 * c) * 4096 + f * 8);
    }
    asm volatile("cp.async.commit_group;" ::: "memory");
}

__global__ __launch_bounds__(512, 1) void gemm_h(
    const __half* __restrict__ A, const __half* __restrict__ Bp,
    void* __restrict__ C0, void* __restrict__ C1, void* __restrict__ C2,
    int M, int N, int K, int fused, int half_out)
{
    extern __shared__ float sm[];
    uint32_t* smw = (uint32_t*)sm;
    const int tid = threadIdx.x;
    const int lane = tid & 31, wid = tid >> 5;
    const int g = lane >> 2, t = lane & 3;
    const int wm = wid & 3, wn = wid >> 2;
    const int tm0 = blockIdx.y * 256, tn0 = blockIdx.x * 128;
    const int np = blockIdx.x;
    const int KC32 = K / 32;
    const int NC = K / 64;
    const uint32_t sb = smem_u32(sm);

    float4 acc[4][4];
#pragma unroll
    for (int i = 0; i < 4; i++)
#pragma unroll
        for (int j = 0; j < 4; j++) acc[i][j] = make_float4(0.f, 0.f, 0.f, 0.f);

    gemm_issue_h(A, Bp, sb, 0, tm0, np, K, KC32, tid);
    gemm_issue_h(A, Bp, sb, 1, tm0, np, K, KC32, tid);
    gemm_issue_h(A, Bp, sb, 2, tm0, np, K, KC32, tid);

    const int r0 = wm * 64 + g;

    for (int c = 0; c < NC; c++) {
        const int rem = NC - 1 - c;
        if (rem >= 2)      asm volatile("cp.async.wait_group 2;" ::: "memory");
        else if (rem == 1) asm volatile("cp.async.wait_group 1;" ::: "memory");
        else               asm volatile("cp.async.wait_group 0;" ::: "memory");
        __syncthreads();

        const uint32_t* As = smw + (c & 3) * GSTW;   // 256 rows x 36 words
        const uint32_t* Bs = As + 9216;              // 2 blocks x 2048 words

#pragma unroll
        for (int kh = 0; kh < 4; kh++) {
            const int kb = kh >> 1, khh = kh & 1;
            uint32_t af[4][4];
#pragma unroll
            for (int mt = 0; mt < 4; mt++) {
                const int rb = (r0 + mt * 16) * 36 + kh * 8 + t;
                af[mt][0] = As[rb];
                af[mt][1] = As[rb + 8 * 36];
                af[mt][2] = As[rb + 4];
                af[mt][3] = As[rb + 8 * 36 + 4];
            }
#pragma unroll
            for (int nt = 0; nt < 4; nt++) {
                uint2 bf = *(const uint2*)&Bs[kb * 2048 +
                    (((wn * 4 + nt) * 2 + khh) * 32 + lane) * 2];
                mma16816(acc[0][nt], af[0], bf);
                mma16816(acc[1][nt], af[1], bf);
                mma16816(acc[2][nt], af[2], bf);
                mma16816(acc[3][nt], af[3], bf);
            }
        }

        if (c + 3 < NC)
            gemm_issue_h(A, Bp, sb, c + 3, tm0, np, K, KC32, tid);
    }

    void* Cd; int ldc, coff;
    if (!fused)            { Cd = C0; ldc = N;    coff = 0;    }
    else if (tn0 < 2048)   { Cd = C0; ldc = 2048; coff = 0;    }
    else if (tn0 < 2560)   { Cd = C1; ldc = 512;  coff = 2048; }
    else                   { Cd = C2; ldc = 512;  coff = 2560; }

#pragma unroll
    for (int mt = 0; mt < 4; mt++) {
#pragma unroll
        for (int nt = 0; nt < 4; nt++) {
            int row = tm0 + wm * 64 + mt * 16 + g;
            int col = tn0 + wn * 32 + nt * 8 + t * 2 - coff;
            float4 a = acc[mt][nt];
            if (half_out) {
                uint32_t* H = (uint32_t*)Cd;
                H[((size_t)row * ldc + col) >> 1]       = packh2(a.x, a.y);
                H[((size_t)(row + 8) * ldc + col) >> 1] = packh2(a.z, a.w);
            } else {
                float* F = (float*)Cd;
                *(float2*)&F[(size_t)row * ldc + col] = make_float2(a.x, a.y);
                *(float2*)&F[(size_t)(row + 8) * ldc + col] = make_float2(a.z, a.w);
            }
        }
    }
}

// ---------------------------------------------------------------------------
// RoPE in place on fp16 q (folds 1/sqrt(HD)) and fp16 k.
// ---------------------------------------------------------------------------
__global__ void rope_h(__half* __restrict__ q, __half* __restrict__ k)
{
    const int NQ = BATCH * SQ * NH * 64;
    const int NK = BATCH * SQ * NKV * 64;
    int i = blockIdx.x * blockDim.x + threadIdx.x;
    if (i >= NQ + NK) return;

    __half* base;
    int d, s;
    float scale;
    if (i < NQ) {
        d = i & 63;
        int rest = i >> 6;
        s = (rest >> 4) & (SQ - 1);
        base = q + (size_t)rest * HD;
        scale = 0.08838834764831845f;
    } else {
        int j = i - NQ;
        d = j & 63;
        int rest = j >> 6;
        s = (rest >> 2) & (SQ - 1);
        base = k + (size_t)rest * HD;
        scale = 1.0f;
    }
    float inv_freq = powf(10000.0f, -(float)d * (1.0f / 64.0f));
    float ang = (float)s * inv_freq;
    float c = cosf(ang), sn = sinf(ang);
    float a = __half2float(base[d]), b = __half2float(base[d + 64]);
    base[d]      = __float2half((a * c - b * sn) * scale);
    base[d + 64] = __float2half((b * c + a * sn) * scale);
}

// ---------------------------------------------------------------------------
// V transpose: v fp16 [B,S,NKV,HD] -> vt fp16 [B,NKV,HD,SQ]
// ---------------------------------------------------------------------------
__global__ void vt_kernel(const __half* __restrict__ v, __half* __restrict__ vt)
{
    __shared__ float tile[32][33];
    const int s0 = blockIdx.x * 32, d0 = blockIdx.y * 32;
    const int bk = blockIdx.z;
    const int x = threadIdx.x, y = threadIdx.y;
#pragma unroll
    for (int i = 0; i < 32; i += 8)
        tile[y + i][x] = __half2float(
            v[((size_t)(bk / NKV * SQ + s0 + y + i) * NKV + (bk % NKV)) * HD + d0 + x]);
    __syncthreads();
#pragma unroll
    for (int i = 0; i < 32; i += 8)
        vt[((size_t)bk * HD + d0 + y + i) * SQ + s0 + x] = __float2half(tile[x][y + i]);
}

// ---------------------------------------------------------------------------
// FP16 flash attention v4 (unchanged from R10, passing):
// 8 warps x 16 q-rows, register-resident P, 1 sync/tile, 2 CTAs/SM.
// ---------------------------------------------------------------------------
#define AQS 0
#define AK0 8704
#define AK1 13056
#define AV0 17408
#define AV1 22016
#define ATT_SMEM (26624 * 4)

__global__ __launch_bounds__(256, 2) void attn_h(
    const __half* __restrict__ qh, const __half* __restrict__ kh,
    const __half* __restrict__ vth, __half* __restrict__ outh)
{
    extern __shared__ float sm[];
    uint32_t* smw = (uint32_t*)sm;
    const uint32_t sb = smem_u32(sm);
    const int tid = threadIdx.x;
    const int lane = tid & 31, wid = tid >> 5;
    const int g = lane >> 2, t = lane & 3;
    const int qt = gridDim.x - 1 - blockIdx.x;   // LPT
    const int h = blockIdx.y, b = blockIdx.z;
    const int kvh = h >> 2;
    const int q0 = qt * 128;

    const uint4* q16 = (const uint4*)qh;
    const int krow = tid >> 4, kc16 = tid & 15;
    const int vrow = tid >> 3, vc16 = tid & 7;
    const __half* ksrc = kh + ((size_t)(b * SQ) * NKV + kvh) * HD;
    const __half* vsrc = vth + (size_t)(b * NKV + kvh) * HD * SQ;

#pragma unroll
    for (int i = 0; i < 8; i++) {
        int f = i * 256 + tid;
        int row = f >> 4, c = f & 15;
        uint4 v = q16[((size_t)(b * SQ + q0 + row) * NH + h) * 16 + c];
        *(uint4*)&smw[AQS + row * 68 + c * 4] = v;
    }
#pragma unroll
    for (int i = 0; i < 4; i++) {
        int row = i * 16 + krow;
        cp_async16(sb + (AK0 + row * 68 + kc16 * 4) * 4,
                   ksrc + (size_t)row * NKV * HD + kc16 * 8);
    }
#pragma unroll
    for (int i = 0; i < 4; i++) {
        int row = i * 32 + vrow;
        cp_async16(sb + (AV0 + row * 36 + vc16 * 4) * 4,
                   vsrc + (size_t)row * SQ + vc16 * 8);
    }
    asm volatile("cp.async.commit_group;" ::: "memory");

    float4 oacc[16];
#pragma unroll
    for (int j = 0; j < 16; j++) oacc[j] = make_float4(0.f, 0.f, 0.f, 0.f);
    float m_s[2] = {-1e30f, -1e30f};
    float l_s[2] = {0.f, 0.f};

    const int r0 = wid * 16 + g;
    const int ntiles = 2 * qt + 2;

    for (int kt = 0; kt < ntiles; kt++) {
        const int k0 = kt * 64;
        const uint32_t KB = (kt & 1) ? AK1 : AK0;
        const uint32_t VB = (kt & 1) ? AV1 : AV0;

        asm volatile("cp.async.wait_group 0;" ::: "memory");
        __syncthreads();

        if (kt + 1 < ntiles) {
            const int kk = k0 + 64;
            const uint32_t KBn = (kt & 1) ? AK0 : AK1;
            const uint32_t VBn = (kt & 1) ? AV0 : AV1;
#pragma unroll
            for (int i = 0; i < 4; i++) {
                int row = i * 16 + krow;
                cp_async16(sb + (KBn + row * 68 + kc16 * 4) * 4,
                           ksrc + (size_t)(kk + row) * NKV * HD + kc16 * 8);
            }
#pragma unroll
            for (int i = 0; i < 4; i++) {
                int row = i * 32 + vrow;
                cp_async16(sb + (VBn + row * 36 + vc16 * 4) * 4,
                           vsrc + (size_t)row * SQ + kk + vc16 * 8);
            }
            asm volatile("cp.async.commit_group;" ::: "memory");
        }

        float4 sacc[8];
#pragma unroll
        for (int j = 0; j < 8; j++) sacc[j] = make_float4(0.f, 0.f, 0.f, 0.f);
#pragma unroll
        for (int ks = 0; ks < 8; ks++) {
            const int c0 = ks * 8 + t;
            uint32_t af[4];
            {
                int rb = AQS + r0 * 68 + c0;
                af[0] = smw[rb];
                af[1] = smw[rb + 68 * 8];
                af[2] = smw[rb + 4];
                af[3] = smw[rb + 68 * 8 + 4];
            }
#pragma unroll
            for (int nt = 0; nt < 8; nt++) {
                int nb = KB + (nt * 8 + g) * 68 + c0;
                uint2 bf = make_uint2(smw[nb], smw[nb + 4]);
                mma16816(sacc[nt], af, bf);
            }
        }

        if (kt >= 2 * qt) {
            const int rowb = q0 + r0;
#pragma unroll
            for (int nt = 0; nt < 8; nt++) {
                int colb = k0 + nt * 8 + 2 * t;
                float* sc = (float*)&sacc[nt];
                if (colb     > rowb)     sc[0] = -1e30f;
                if (colb + 1 > rowb)     sc[1] = -1e30f;
                if (colb     > rowb + 8) sc[2] = -1e30f;
                if (colb + 1 > rowb + 8) sc[3] = -1e30f;
            }
        }

        float rmax[2] = {-1e30f, -1e30f};
#pragma unroll
        for (int nt = 0; nt < 8; nt++) {
            rmax[0] = fmaxf(rmax[0], fmaxf(sacc[nt].x, sacc[nt].y));
            rmax[1] = fmaxf(rmax[1], fmaxf(sacc[nt].z, sacc[nt].w));
        }
#pragma unroll
        for (int hf = 0; hf < 2; hf++) {
            float x = rmax[hf];
            x = fmaxf(x, __shfl_xor_sync(0xffffffffu, x, 1));
            x = fmaxf(x, __shfl_xor_sync(0xffffffffu, x, 2));
            rmax[hf] = x;
        }
        float alpha[2];
#pragma unroll
        for (int hf = 0; hf < 2; hf++) {
            float mn = fmaxf(m_s[hf], rmax[hf]);
            alpha[hf] = __expf(m_s[hf] - mn);
            m_s[hf] = mn;
        }

        uint32_t pa[4][4];
        float rsum[2] = {0.f, 0.f};
#pragma unroll
        for (int ks = 0; ks < 4; ks++) {
            float4 s0 = sacc[2 * ks], s1 = sacc[2 * ks + 1];
            float p00 = __expf(s0.x - m_s[0]), p01 = __expf(s0.y - m_s[0]);
            float p02 = __expf(s0.z - m_s[1]), p03 = __expf(s0.w - m_s[1]);
            float p10 = __expf(s1.x - m_s[0]), p11 = __expf(s1.y - m_s[0]);
            float p12 = __expf(s1.z - m_s[1]), p13 = __expf(s1.w - m_s[1]);
            rsum[0] += p00 + p01 + p10 + p11;
            rsum[1] += p02 + p03 + p12 + p13;
            pa[ks][0] = packh2(p00, p01);
            pa[ks][1] = packh2(p02, p03);
            pa[ks][2] = packh2(p10, p11);
            pa[ks][3] = packh2(p12, p13);
        }
#pragma unroll
        for (int hf = 0; hf < 2; hf++) {
            float x = rsum[hf];
            x += __shfl_xor_sync(0xffffffffu, x, 1);
            x += __shfl_xor_sync(0xffffffffu, x, 2);
            l_s[hf] = l_s[hf] * alpha[hf] + x;
        }
#pragma unroll
        for (int nt = 0; nt < 16; nt++) {
            oacc[nt].x *= alpha[0];
            oacc[nt].y *= alpha[0];
            oacc[nt].z *= alpha[1];
            oacc[nt].w *= alpha[1];
        }

#pragma unroll
        for (int ks = 0; ks < 4; ks++) {
            const int c0 = ks * 8 + t;
#pragma unroll
            for (int nt = 0; nt < 16; nt++) {
                int nb = VB + (nt * 8 + g) * 36 + c0;
                uint2 bf = make_uint2(smw[nb], smw[nb + 4]);
                mma16816(oacc[nt], pa[ks], bf);
            }
        }
    }

    uint32_t* outw = (uint32_t*)outh;
    const float i0 = 1.f / l_s[0], i1 = 1.f / l_s[1];
    const int row = q0 + r0;
#pragma unroll
    for (int nt = 0; nt < 16; nt++) {
        int cw = h * 64 + nt * 4 + t;
        float4 o = oacc[nt];
        outw[(size_t)(b * SQ + row) * 1024 + cw]     = packh2(o.x * i0, o.y * i0);
        outw[(size_t)(b * SQ + row + 8) * 1024 + cw] = packh2(o.z * i1, o.w * i1);
    }
}

// ---------------------------------------------------------------------------
extern "C" void kernel_launch(void* const* d_in, const int* in_sizes, int n_in,
                              void* d_out, int out_size)
{
    const float* x  = (const float*)d_in[0];
    const float* Wq = (const float*)d_in[1];
    const float* Wk = (const float*)d_in[2];
    const float* Wv = (const float*)d_in[3];
    const float* Wo = (const float*)d_in[4];

    __half *xh, *qh, *kh, *vh, *vth, *ah, *wh, *wo;
    cudaGetSymbolAddress((void**)&xh, g_xh);
    cudaGetSymbolAddress((void**)&qh, g_qh);
    cudaGetSymbolAddress((void**)&kh, g_kh);
    cudaGetSymbolAddress((void**)&vh, g_vh);
    cudaGetSymbolAddress((void**)&vth, g_vth);
    cudaGetSymbolAddress((void**)&ah, g_ah);
    cudaGetSymbolAddress((void**)&wh, g_wh);
    cudaGetSymbolAddress((void**)&wo, g_wo);

    const int M = BATCH * SQ;   // 4096

    cudaFuncSetAttribute(gemm_h, cudaFuncAttributeMaxDynamicSharedMemorySize,
                         GEMM_SMEM);
    cudaFuncSetAttribute(attn_h, cudaFuncAttributeMaxDynamicSharedMemorySize,
                         ATT_SMEM);

    // x -> fp16; pack all four weights (one launch)
    cvt_x<<<(M * EB / 4 + 255) / 256, 256>>>(x, xh, M * EB / 4);
    pack_all<<<(5242880 + 255) / 256, 256>>>(Wq, Wk, Wv, Wo, wh, wo);

    // Fused QKV projection -> fp16 q/k/v
    gemm_h<<<dim3(3072 / 128, M / 256), 512, GEMM_SMEM>>>(
        xh, wh, qh, kh, vh, M, 3072, EB, 1, 1);

    // RoPE in place; V transpose
    int npairs = BATCH * SQ * (NH + NKV) * 64;
    rope_h<<<(npairs + 255) / 256, 256>>>(qh, kh);
    vt_kernel<<<dim3(SQ / 32, HD / 32, BATCH * NKV), dim3(32, 8)>>>(vh, vth);

    // Flash attention v4
    attn_h<<<dim3(SQ / 128, NH, BATCH), 256, ATT_SMEM>>>(qh, kh, vth, ah);

    // Output projection (fp32 out)
    gemm_h<<<dim3(EB / 128, M / 256), 512, GEMM_SMEM>>>(
        ah, wo, d_out, nullptr, nullptr, M, EB, EB, 0, 0);
}